// round 1
// baseline (speedup 1.0000x reference)
#include <cuda_runtime.h>
#include <math.h>

// ---------------------------------------------------------------------------
// FilterGNN: h = tanh(tanh(x@W1^T)@W2^T)@W3^T ; out = scatter_mean(h[src]*gate, dst)
// Round 1: correct fp32 SIMT baseline.
//   - 3x register-tiled 128x128x8 fp32 GEMM (NT: A[M,K] row-major, W[N,K] row-major)
//   - fused bias + tanh epilogue
//   - warp-per-edge gated scatter with float atomics (gate==0 edges skip traffic)
//   - finalize: divide by max(count,1)
// Scratch in __device__ globals (no allocations anywhere).
// ---------------------------------------------------------------------------

#define MAXN 100000

__device__ float g_h1[MAXN * 512];
__device__ float g_h2[MAXN * 256];
__device__ float g_h [MAXN * 128];
__device__ float g_cnt[MAXN];

// C[M,N] = act(A[M,K] @ W[N,K]^T + bias[N]),  N % 128 == 0, K % 8 == 0.
template<int DO_TANH>
__global__ __launch_bounds__(256, 2)
void gemm_nt(const float* __restrict__ A, const float* __restrict__ W,
             const float* __restrict__ bias, float* __restrict__ C,
             int M, int N, int K)
{
    __shared__ float As[2][8][128];   // [buf][k][m]
    __shared__ float Bs[2][8][128];   // [buf][k][n]

    const int tid    = threadIdx.x;
    const int mBlock = blockIdx.y * 128;
    const int nBlock = blockIdx.x * 128;

    // tile loaders: 128 rows x 8 k per chunk; thread -> (row, 4 of 8 k)
    const int loadRow = tid >> 1;          // 0..127
    const int loadK   = (tid & 1) * 4;     // 0 or 4

    // compute quadrants: 4+4 rows, 4+4 cols per thread (conflict-free smem reads)
    const int tm = (tid >> 4) * 4;         // 0..60
    const int tn = (tid & 15) * 4;         // 0..60

    float acc[8][8];
    #pragma unroll
    for (int i = 0; i < 8; i++)
        #pragma unroll
        for (int j = 0; j < 8; j++) acc[i][j] = 0.0f;

    const int KT = K >> 3;
    const int arow = mBlock + loadRow;
    const int brow = nBlock + loadRow;

    float4 stageA, stageB;
    // preload tile 0
    stageA = (arow < M) ? *(const float4*)(A + (size_t)arow * K + loadK)
                        : make_float4(0.f, 0.f, 0.f, 0.f);
    stageB = *(const float4*)(W + (size_t)brow * K + loadK);
    As[0][loadK + 0][loadRow] = stageA.x;
    As[0][loadK + 1][loadRow] = stageA.y;
    As[0][loadK + 2][loadRow] = stageA.z;
    As[0][loadK + 3][loadRow] = stageA.w;
    Bs[0][loadK + 0][loadRow] = stageB.x;
    Bs[0][loadK + 1][loadRow] = stageB.y;
    Bs[0][loadK + 2][loadRow] = stageB.z;
    Bs[0][loadK + 3][loadRow] = stageB.w;
    __syncthreads();

    int cur = 0;
    for (int kt = 0; kt < KT; kt++) {
        if (kt + 1 < KT) {
            const int koff = (kt + 1) * 8 + loadK;
            stageA = (arow < M) ? *(const float4*)(A + (size_t)arow * K + koff)
                                : make_float4(0.f, 0.f, 0.f, 0.f);
            stageB = *(const float4*)(W + (size_t)brow * K + koff);
        }
        #pragma unroll
        for (int k = 0; k < 8; k++) {
            float a[8], b[8];
            *(float4*)(a)     = *(const float4*)&As[cur][k][tm];
            *(float4*)(a + 4) = *(const float4*)&As[cur][k][tm + 64];
            *(float4*)(b)     = *(const float4*)&Bs[cur][k][tn];
            *(float4*)(b + 4) = *(const float4*)&Bs[cur][k][tn + 64];
            #pragma unroll
            for (int i = 0; i < 8; i++)
                #pragma unroll
                for (int j = 0; j < 8; j++)
                    acc[i][j] = fmaf(a[i], b[j], acc[i][j]);
        }
        if (kt + 1 < KT) {
            const int nxt = cur ^ 1;
            As[nxt][loadK + 0][loadRow] = stageA.x;
            As[nxt][loadK + 1][loadRow] = stageA.y;
            As[nxt][loadK + 2][loadRow] = stageA.z;
            As[nxt][loadK + 3][loadRow] = stageA.w;
            Bs[nxt][loadK + 0][loadRow] = stageB.x;
            Bs[nxt][loadK + 1][loadRow] = stageB.y;
            Bs[nxt][loadK + 2][loadRow] = stageB.z;
            Bs[nxt][loadK + 3][loadRow] = stageB.w;
        }
        __syncthreads();
        cur ^= 1;
    }

    float bn[8];
    *(float4*)(bn)     = *(const float4*)(bias + nBlock + tn);
    *(float4*)(bn + 4) = *(const float4*)(bias + nBlock + tn + 64);

    #pragma unroll
    for (int i = 0; i < 8; i++) {
        const int row = mBlock + tm + ((i < 4) ? i : (60 + i)); // i>=4 -> +64+(i-4)
        if (row < M) {
            float v[8];
            #pragma unroll
            for (int j = 0; j < 8; j++) {
                float t = acc[i][j] + bn[j];
                v[j] = DO_TANH ? tanhf(t) : t;
            }
            float* cp = C + (size_t)row * N + nBlock;
            *(float4*)(cp + tn)      = *(float4*)(v);
            *(float4*)(cp + tn + 64) = *(float4*)(v + 4);
        }
    }
}

// One warp per edge. Count every edge; move/scatter data only when gate > 0.
__global__ void scatter_accum(const float* __restrict__ h,
                              const float* __restrict__ alpha,
                              const int* __restrict__ ei,
                              float* __restrict__ out,
                              int E)
{
    const int gt   = blockIdx.x * blockDim.x + threadIdx.x;
    const int e    = gt >> 5;
    const int lane = threadIdx.x & 31;
    if (e >= E) return;

    const int dst = ei[E + e];
    if (lane == 0) atomicAdd(&g_cnt[dst], 1.0f);

    const float gate = 2.0f * fmaxf(alpha[e] - 0.5f, 0.0f);
    if (gate > 0.0f) {
        const int src = ei[e];
        float4 v = *(const float4*)(h + (size_t)src * 128 + lane * 4);
        float* op = out + (size_t)dst * 128 + lane * 4;
        atomicAdd(op + 0, v.x * gate);
        atomicAdd(op + 1, v.y * gate);
        atomicAdd(op + 2, v.z * gate);
        atomicAdd(op + 3, v.w * gate);
    }
}

__global__ void finalize_mean(float* __restrict__ out, int total)
{
    const int i = blockIdx.x * blockDim.x + threadIdx.x;
    if (i < total) {
        const float c = g_cnt[i >> 7];
        out[i] = out[i] / fmaxf(c, 1.0f);
    }
}

extern "C" void kernel_launch(void* const* d_in, const int* in_sizes, int n_in,
                              void* d_out, int out_size)
{
    const float* x     = (const float*)d_in[0];
    const float* alpha = (const float*)d_in[1];
    const int*   ei    = (const int*)  d_in[2];
    // d_in[3] = norm (unused by the reference math)
    const float* W1 = (const float*)d_in[4];
    const float* b1 = (const float*)d_in[5];
    const float* W2 = (const float*)d_in[6];
    const float* b2 = (const float*)d_in[7];
    const float* W3 = (const float*)d_in[8];
    const float* b3 = (const float*)d_in[9];
    float* out = (float*)d_out;

    const int N = in_sizes[0] / 256;   // nodes
    const int E = in_sizes[1];         // edges

    float *h1, *h2, *h, *cnt;
    cudaGetSymbolAddress((void**)&h1,  g_h1);
    cudaGetSymbolAddress((void**)&h2,  g_h2);
    cudaGetSymbolAddress((void**)&h,   g_h);
    cudaGetSymbolAddress((void**)&cnt, g_cnt);

    cudaMemsetAsync(out, 0, (size_t)N * 128 * sizeof(float));
    cudaMemsetAsync(cnt, 0, (size_t)N * sizeof(float));

    const int mt = (N + 127) / 128;
    gemm_nt<1><<<dim3(512 / 128, mt), 256>>>(x,  W1, b1, h1, N, 512, 256);
    gemm_nt<1><<<dim3(256 / 128, mt), 256>>>(h1, W2, b2, h2, N, 256, 512);
    gemm_nt<0><<<dim3(128 / 128, mt), 256>>>(h2, W3, b3, h,  N, 128, 256);

    scatter_accum<<<(E * 32 + 255) / 256, 256>>>(h, alpha, ei, out, E);

    const int total = N * 128;
    finalize_mean<<<(total + 255) / 256, 256>>>(out, total);
}

// round 4
// speedup vs baseline: 1.7515x; 1.7515x over previous
#include <cuda_runtime.h>
#include <cuda_fp16.h>
#include <math.h>
#include <stdint.h>

// ---------------------------------------------------------------------------
// FilterGNN round 4: mma.sync (HMMA) split-fp16 GEMMs, 3-term fp32 accumulate.
//   h1 = tanh(x@W1^T); h2 = tanh(h1@W2^T); h = h2@W3^T
//   out = scatter_mean(h[src] * gate, dst)
// tcgen05 unusable (harness PTX targets sm_103, not sm_103a) -> legacy
// mma.sync.m16n8k16 path with cp.async 4-stage pipeline + ldmatrix.
// ---------------------------------------------------------------------------

#define MAXN 100000

__device__ __align__(16) __half g_xhi [MAXN * 256];
__device__ __align__(16) __half g_xlo [MAXN * 256];
__device__ __align__(16) __half g_h1hi[MAXN * 512];
__device__ __align__(16) __half g_h1lo[MAXN * 512];
__device__ __align__(16) __half g_h2hi[MAXN * 256];
__device__ __align__(16) __half g_h2lo[MAXN * 256];
__device__ __align__(16) float  g_h   [MAXN * 128];
__device__ float  g_cnt [MAXN];
__device__ __align__(16) __half g_w1hi[512 * 256], g_w1lo[512 * 256];
__device__ __align__(16) __half g_w2hi[256 * 512], g_w2lo[256 * 512];
__device__ __align__(16) __half g_w3hi[128 * 256], g_w3lo[128 * 256];

// ------------------------------- helpers -----------------------------------

__device__ __forceinline__ uint32_t smem_u32(const void* p) {
    uint32_t a;
    asm("{ .reg .u64 t; cvta.to.shared.u64 t, %1; cvt.u32.u64 %0, t; }"
        : "=r"(a) : "l"(p));
    return a;
}

#define SWZ(off) ((off) ^ (((off) >> 3) & 0x70))

__device__ __forceinline__ void cp16(uint32_t dst, const void* src) {
    asm volatile("cp.async.cg.shared.global [%0], [%1], 16;\n"
                 :: "r"(dst), "l"(src));
}
__device__ __forceinline__ void cp16z(uint32_t dst, const void* src, bool valid) {
    asm volatile("cp.async.cg.shared.global [%0], [%1], 16, %2;\n"
                 :: "r"(dst), "l"(src), "r"(valid ? 16u : 0u));
}
#define CP_COMMIT()  asm volatile("cp.async.commit_group;\n" ::: "memory")
#define CP_WAIT(n)   asm volatile("cp.async.wait_group %0;\n" :: "n"(n) : "memory")

__device__ __forceinline__ void ldm_x4(uint32_t r[4], uint32_t addr) {
    asm volatile("ldmatrix.sync.aligned.m8n8.x4.shared.b16 {%0,%1,%2,%3}, [%4];"
                 : "=r"(r[0]), "=r"(r[1]), "=r"(r[2]), "=r"(r[3]) : "r"(addr));
}

__device__ __forceinline__ void mma16816(float c[4], const uint32_t a[4],
                                         uint32_t b0, uint32_t b1) {
    asm volatile(
        "mma.sync.aligned.m16n8k16.row.col.f32.f16.f16.f32 "
        "{%0,%1,%2,%3}, {%4,%5,%6,%7}, {%8,%9}, {%0,%1,%2,%3};"
        : "+f"(c[0]), "+f"(c[1]), "+f"(c[2]), "+f"(c[3])
        : "r"(a[0]), "r"(a[1]), "r"(a[2]), "r"(a[3]), "r"(b0), "r"(b1));
}

// ------------------------------ split kernel -------------------------------

__global__ void split_kernel(const float* __restrict__ a,
                             __half* __restrict__ hi,
                             __half* __restrict__ lo, int n4)
{
    int i = blockIdx.x * blockDim.x + threadIdx.x;
    if (i >= n4) return;
    float4 v = ((const float4*)a)[i];
    float f[4] = {v.x, v.y, v.z, v.w};
    __half h[4], l[4];
    #pragma unroll
    for (int p = 0; p < 4; p++) {
        h[p] = __float2half_rn(f[p]);
        l[p] = __float2half_rn(f[p] - __half2float(h[p]));
    }
    ((uint2*)hi)[i] = *(uint2*)h;
    ((uint2*)lo)[i] = *(uint2*)l;
}

// --------------------------------- GEMM ------------------------------------
// C[128 x NT] tile. A[M,K] row-major fp16 split; B(N,K) row-major fp16 split.
// Virtual K' = 3K: pass 0 = Ah*Bh, 1 = Al*Bh, 2 = Ah*Bl. 64-half chunks.

template<int NT>
__device__ __forceinline__ void fill_chunk(
    uint32_t sA, uint32_t sB,
    const __half* __restrict__ Ahi, const __half* __restrict__ Alo,
    const __half* __restrict__ Bhi, const __half* __restrict__ Blo,
    int c, int K, int M, int mBlock, int nBlock, int tid)
{
    constexpr int THREADS = 128 * (NT / 64);
    const int c64  = c << 6;
    const int pass = c64 / K;
    const int kk   = c64 - pass * K;
    const __half* Asrc = (pass == 1) ? Alo : Ahi;
    const __half* Bsrc = (pass == 2) ? Blo : Bhi;

    #pragma unroll
    for (int i = 0; i < 1024 / THREADS; i++) {            // A: 128 rows x 128B
        int s = tid + i * THREADS;
        int row = s >> 3, byte = (s & 7) << 4;
        int grow = mBlock + row;
        bool v = grow < M;
        const char* src = (const char*)(Asrc + (size_t)(v ? grow : 0) * K + kk) + byte;
        cp16z(sA + SWZ((row << 7) + byte), src, v);
    }
    #pragma unroll
    for (int i = 0; i < (NT * 8) / THREADS; i++) {        // B: NT rows x 128B
        int s = tid + i * THREADS;
        int row = s >> 3, byte = (s & 7) << 4;
        const char* src = (const char*)(Bsrc + (size_t)(nBlock + row) * K + kk) + byte;
        cp16(sB + SWZ((row << 7) + byte), src);
    }
}

template<int NT, int STAGES, bool TANH, bool SPLIT_OUT>
__global__ void __launch_bounds__(128 * (NT / 64))
gemm_mma(const __half* __restrict__ Ahi, const __half* __restrict__ Alo,
         const __half* __restrict__ Bhi, const __half* __restrict__ Blo,
         const float* __restrict__ bias,
         __half* __restrict__ Ohi, __half* __restrict__ Olo,
         float* __restrict__ Of,
         int M, int Nn, int K)
{
    extern __shared__ char smem[];
    constexpr int A_BYTES = 128 * 128;
    constexpr int B_BYTES = NT * 128;
    constexpr int STAGE   = A_BYTES + B_BYTES;

    const int tid = threadIdx.x;
    const int wid = tid >> 5;
    const int lid = tid & 31;
    const int wm  = wid & 3;            // warp M index (0..3), tile 32 rows
    const int wn  = wid >> 2;           // warp N index, tile 64 cols
    const int mBlock = blockIdx.y * 128;
    const int nBlock = blockIdx.x * NT;

    const uint32_t sbase = smem_u32(smem);

    float acc[2][8][4];
    #pragma unroll
    for (int i = 0; i < 2; i++)
        #pragma unroll
        for (int j = 0; j < 8; j++)
            #pragma unroll
            for (int q = 0; q < 4; q++) acc[i][j][q] = 0.0f;

    const int NC = (3 * K) >> 6;

    // prologue: fill stages 0..STAGES-2
    #pragma unroll
    for (int s = 0; s < STAGES - 1; s++) {
        if (s < NC)
            fill_chunk<NT>(sbase + s * STAGE, sbase + s * STAGE + A_BYTES,
                           Ahi, Alo, Bhi, Blo, s, K, M, mBlock, nBlock, tid);
        CP_COMMIT();
    }

    // lane-constant ldmatrix address pieces
    const int aRow  = lid & 15;
    const int aByte = (lid >> 4) << 4;
    const int bRow  = (((lid >> 4) & 1) << 3) + (lid & 7);
    const int bByte = ((lid >> 3) & 1) << 4;

    for (int c = 0; c < NC; c++) {
        const int fs = c + STAGES - 1;
        if (fs < NC) {
            const int st = fs % STAGES;
            fill_chunk<NT>(sbase + st * STAGE, sbase + st * STAGE + A_BYTES,
                           Ahi, Alo, Bhi, Blo, fs, K, M, mBlock, nBlock, tid);
        }
        CP_COMMIT();
        CP_WAIT(STAGES - 1);
        __syncthreads();

        const uint32_t stA = sbase + (c % STAGES) * STAGE;
        const uint32_t stB = stA + A_BYTES;

        #pragma unroll
        for (int s = 0; s < 4; s++) {               // 4 x k16 per 64-half chunk
            uint32_t a[2][4], b[4][4];
            #pragma unroll
            for (int mi = 0; mi < 2; mi++) {
                const int row = wm * 32 + mi * 16 + aRow;
                const uint32_t off = (uint32_t)((32 * s + aByte) ^ ((row & 7) << 4));
                ldm_x4(a[mi], stA + (row << 7) + off);
            }
            #pragma unroll
            for (int g = 0; g < 4; g++) {
                const int row = wn * 64 + g * 16 + bRow;
                const uint32_t off = (uint32_t)((32 * s + bByte) ^ ((row & 7) << 4));
                ldm_x4(b[g], stB + (row << 7) + off);
            }
            #pragma unroll
            for (int mi = 0; mi < 2; mi++)
                #pragma unroll
                for (int ni = 0; ni < 8; ni++)
                    mma16816(acc[mi][ni], a[mi], b[ni >> 1][(ni & 1) * 2],
                             b[ni >> 1][(ni & 1) * 2 + 1]);
        }
        __syncthreads();
    }

    // ------------------------------ epilogue --------------------------------
    const int lid4 = lid >> 2;
    const int lq   = (lid & 3) * 2;
    #pragma unroll
    for (int mi = 0; mi < 2; mi++) {
        #pragma unroll
        for (int rr = 0; rr < 2; rr++) {
            const int row = mBlock + wm * 32 + mi * 16 + rr * 8 + lid4;
            if (row >= M) continue;
            #pragma unroll
            for (int ni = 0; ni < 8; ni++) {
                const int col = nBlock + wn * 64 + ni * 8 + lq;
                float v0 = acc[mi][ni][rr * 2 + 0] + __ldg(&bias[col]);
                float v1 = acc[mi][ni][rr * 2 + 1] + __ldg(&bias[col + 1]);
                if (TANH) { v0 = tanhf(v0); v1 = tanhf(v1); }
                if (SPLIT_OUT) {
                    __half h0 = __float2half_rn(v0), h1 = __float2half_rn(v1);
                    __half l0 = __float2half_rn(v0 - __half2float(h0));
                    __half l1 = __float2half_rn(v1 - __half2float(h1));
                    *(__half2*)(Ohi + (size_t)row * Nn + col) = __halves2half2(h0, h1);
                    *(__half2*)(Olo + (size_t)row * Nn + col) = __halves2half2(l0, l1);
                } else {
                    *(float2*)(Of + (size_t)row * Nn + col) = make_float2(v0, v1);
                }
            }
        }
    }
}

// ------------------------------ scatter-mean -------------------------------

__global__ void scatter_accum(const float* __restrict__ h,
                              const float* __restrict__ alpha,
                              const int* __restrict__ ei,
                              float* __restrict__ out,
                              int E)
{
    const int gt   = blockIdx.x * blockDim.x + threadIdx.x;
    const int e    = gt >> 5;
    const int lane = threadIdx.x & 31;
    if (e >= E) return;

    const int dst = ei[E + e];
    if (lane == 0) atomicAdd(&g_cnt[dst], 1.0f);

    const float gate = 2.0f * fmaxf(alpha[e] - 0.5f, 0.0f);
    if (gate > 0.0f) {
        const int src = ei[e];
        float4 v = *(const float4*)(h + (size_t)src * 128 + lane * 4);
        float* op = out + (size_t)dst * 128 + lane * 4;
        atomicAdd(op + 0, v.x * gate);
        atomicAdd(op + 1, v.y * gate);
        atomicAdd(op + 2, v.z * gate);
        atomicAdd(op + 3, v.w * gate);
    }
}

__global__ void finalize_mean(float* __restrict__ out, int total)
{
    const int i = blockIdx.x * blockDim.x + threadIdx.x;
    if (i < total) {
        const float c = g_cnt[i >> 7];
        out[i] = out[i] / fmaxf(c, 1.0f);
    }
}

// --------------------------------- launch ----------------------------------

extern "C" void kernel_launch(void* const* d_in, const int* in_sizes, int n_in,
                              void* d_out, int out_size)
{
    const float* x     = (const float*)d_in[0];
    const float* alpha = (const float*)d_in[1];
    const int*   ei    = (const int*)  d_in[2];
    const float* W1 = (const float*)d_in[4];
    const float* b1 = (const float*)d_in[5];
    const float* W2 = (const float*)d_in[6];
    const float* b2 = (const float*)d_in[7];
    const float* W3 = (const float*)d_in[8];
    const float* b3 = (const float*)d_in[9];
    float* out = (float*)d_out;

    const int N = in_sizes[0] / 256;   // nodes
    const int E = in_sizes[1];         // edges

    __half *xhi, *xlo, *h1hi, *h1lo, *h2hi, *h2lo;
    __half *w1hi, *w1lo, *w2hi, *w2lo, *w3hi, *w3lo;
    float *h, *cnt;
    cudaGetSymbolAddress((void**)&xhi,  g_xhi);
    cudaGetSymbolAddress((void**)&xlo,  g_xlo);
    cudaGetSymbolAddress((void**)&h1hi, g_h1hi);
    cudaGetSymbolAddress((void**)&h1lo, g_h1lo);
    cudaGetSymbolAddress((void**)&h2hi, g_h2hi);
    cudaGetSymbolAddress((void**)&h2lo, g_h2lo);
    cudaGetSymbolAddress((void**)&w1hi, g_w1hi);
    cudaGetSymbolAddress((void**)&w1lo, g_w1lo);
    cudaGetSymbolAddress((void**)&w2hi, g_w2hi);
    cudaGetSymbolAddress((void**)&w2lo, g_w2lo);
    cudaGetSymbolAddress((void**)&w3hi, g_w3hi);
    cudaGetSymbolAddress((void**)&w3lo, g_w3lo);
    cudaGetSymbolAddress((void**)&h,    g_h);
    cudaGetSymbolAddress((void**)&cnt,  g_cnt);

    // smem: STAGES * (128 + NT) * 128 bytes
    const int SMEM_256 = 4 * (128 + 256) * 128;   // 196608
    const int SMEM_128 = 4 * (128 + 128) * 128;   // 131072
    cudaFuncSetAttribute(gemm_mma<256, 4, true,  true >,
                         cudaFuncAttributeMaxDynamicSharedMemorySize, SMEM_256);
    cudaFuncSetAttribute(gemm_mma<128, 4, false, false>,
                         cudaFuncAttributeMaxDynamicSharedMemorySize, SMEM_128);

    cudaMemsetAsync(out, 0, (size_t)N * 128 * sizeof(float));
    cudaMemsetAsync(cnt, 0, (size_t)N * sizeof(float));

    // split inputs / weights into fp16 hi+lo
    {
        int n4 = (N * 256) / 4;
        split_kernel<<<(n4 + 255) / 256, 256>>>(x, xhi, xlo, n4);
        split_kernel<<<(512 * 256 / 4 + 255) / 256, 256>>>(W1, w1hi, w1lo, 512 * 256 / 4);
        split_kernel<<<(256 * 512 / 4 + 255) / 256, 256>>>(W2, w2hi, w2lo, 256 * 512 / 4);
        split_kernel<<<(128 * 256 / 4 + 255) / 256, 256>>>(W3, w3hi, w3lo, 128 * 256 / 4);
    }

    const int mt = (N + 127) / 128;
    gemm_mma<256, 4, true,  true ><<<dim3(2, mt), 512, SMEM_256>>>(
        xhi, xlo, w1hi, w1lo, b1, h1hi, h1lo, nullptr, N, 512, 256);
    gemm_mma<256, 4, true,  true ><<<dim3(1, mt), 512, SMEM_256>>>(
        h1hi, h1lo, w2hi, w2lo, b2, h2hi, h2lo, nullptr, N, 256, 512);
    gemm_mma<128, 4, false, false><<<dim3(1, mt), 256, SMEM_128>>>(
        h2hi, h2lo, w3hi, w3lo, b3, nullptr, nullptr, h, N, 128, 256);

    scatter_accum<<<(E * 32 + 255) / 256, 256>>>(h, alpha, ei, out, E);

    const int total = N * 128;
    finalize_mean<<<(total + 255) / 256, 256>>>(out, total);
}

// round 5
// speedup vs baseline: 1.9592x; 1.1186x over previous
#include <cuda_runtime.h>
#include <cuda_fp16.h>
#include <math.h>
#include <stdint.h>

// ---------------------------------------------------------------------------
// FilterGNN round 5: HMMA split-fp16 GEMMs (unchanged from R4) + CSR scatter.
//   scatter-mean now: hist -> exclusive scan -> compact surviving edges ->
//   warp-per-dst gather (no fp32 atomics, no out memset, no finalize).
// Launch order arranged so ncu (-s 5 -c 1) captures gemm1.
// ---------------------------------------------------------------------------

#define MAXN 100000
#define MAXE 640000

__device__ __align__(16) __half g_xhi [MAXN * 256];
__device__ __align__(16) __half g_xlo [MAXN * 256];
__device__ __align__(16) __half g_h1hi[MAXN * 512];
__device__ __align__(16) __half g_h1lo[MAXN * 512];
__device__ __align__(16) __half g_h2hi[MAXN * 256];
__device__ __align__(16) __half g_h2lo[MAXN * 256];
__device__ __align__(16) float  g_h   [MAXN * 128];
__device__ __align__(16) __half g_w1hi[512 * 256], g_w1lo[512 * 256];
__device__ __align__(16) __half g_w2hi[256 * 512], g_w2lo[256 * 512];
__device__ __align__(16) __half g_w3hi[128 * 256], g_w3lo[128 * 256];

__device__ int   g_hist[MAXN];
__device__ int   g_off [MAXN];
__device__ int   g_cur [MAXN];
__device__ int   g_part[512];
__device__ uint2 g_packed[MAXE];

// ------------------------------- helpers -----------------------------------

__device__ __forceinline__ uint32_t smem_u32(const void* p) {
    uint32_t a;
    asm("{ .reg .u64 t; cvta.to.shared.u64 t, %1; cvt.u32.u64 %0, t; }"
        : "=r"(a) : "l"(p));
    return a;
}

#define SWZ(off) ((off) ^ (((off) >> 3) & 0x70))

__device__ __forceinline__ void cp16(uint32_t dst, const void* src) {
    asm volatile("cp.async.cg.shared.global [%0], [%1], 16;\n"
                 :: "r"(dst), "l"(src));
}
__device__ __forceinline__ void cp16z(uint32_t dst, const void* src, bool valid) {
    asm volatile("cp.async.cg.shared.global [%0], [%1], 16, %2;\n"
                 :: "r"(dst), "l"(src), "r"(valid ? 16u : 0u));
}
#define CP_COMMIT()  asm volatile("cp.async.commit_group;\n" ::: "memory")
#define CP_WAIT(n)   asm volatile("cp.async.wait_group %0;\n" :: "n"(n) : "memory")

__device__ __forceinline__ void ldm_x4(uint32_t r[4], uint32_t addr) {
    asm volatile("ldmatrix.sync.aligned.m8n8.x4.shared.b16 {%0,%1,%2,%3}, [%4];"
                 : "=r"(r[0]), "=r"(r[1]), "=r"(r[2]), "=r"(r[3]) : "r"(addr));
}

__device__ __forceinline__ void mma16816(float c[4], const uint32_t a[4],
                                         uint32_t b0, uint32_t b1) {
    asm volatile(
        "mma.sync.aligned.m16n8k16.row.col.f32.f16.f16.f32 "
        "{%0,%1,%2,%3}, {%4,%5,%6,%7}, {%8,%9}, {%0,%1,%2,%3};"
        : "+f"(c[0]), "+f"(c[1]), "+f"(c[2]), "+f"(c[3])
        : "r"(a[0]), "r"(a[1]), "r"(a[2]), "r"(a[3]), "r"(b0), "r"(b1));
}

// ------------------------------ split kernel -------------------------------

__global__ void split_kernel(const float* __restrict__ a,
                             __half* __restrict__ hi,
                             __half* __restrict__ lo, int n4)
{
    int i = blockIdx.x * blockDim.x + threadIdx.x;
    if (i >= n4) return;
    float4 v = ((const float4*)a)[i];
    float f[4] = {v.x, v.y, v.z, v.w};
    __half h[4], l[4];
    #pragma unroll
    for (int p = 0; p < 4; p++) {
        h[p] = __float2half_rn(f[p]);
        l[p] = __float2half_rn(f[p] - __half2float(h[p]));
    }
    ((uint2*)hi)[i] = *(uint2*)h;
    ((uint2*)lo)[i] = *(uint2*)l;
}

// --------------------------------- GEMM ------------------------------------

template<int NT>
__device__ __forceinline__ void fill_chunk(
    uint32_t sA, uint32_t sB,
    const __half* __restrict__ Ahi, const __half* __restrict__ Alo,
    const __half* __restrict__ Bhi, const __half* __restrict__ Blo,
    int c, int K, int M, int mBlock, int nBlock, int tid)
{
    constexpr int THREADS = 128 * (NT / 64);
    const int c64  = c << 6;
    const int pass = c64 / K;
    const int kk   = c64 - pass * K;
    const __half* Asrc = (pass == 1) ? Alo : Ahi;
    const __half* Bsrc = (pass == 2) ? Blo : Bhi;

    #pragma unroll
    for (int i = 0; i < 1024 / THREADS; i++) {
        int s = tid + i * THREADS;
        int row = s >> 3, byte = (s & 7) << 4;
        int grow = mBlock + row;
        bool v = grow < M;
        const char* src = (const char*)(Asrc + (size_t)(v ? grow : 0) * K + kk) + byte;
        cp16z(sA + SWZ((row << 7) + byte), src, v);
    }
    #pragma unroll
    for (int i = 0; i < (NT * 8) / THREADS; i++) {
        int s = tid + i * THREADS;
        int row = s >> 3, byte = (s & 7) << 4;
        const char* src = (const char*)(Bsrc + (size_t)(nBlock + row) * K + kk) + byte;
        cp16(sB + SWZ((row << 7) + byte), src);
    }
}

template<int NT, int STAGES, bool TANH, bool SPLIT_OUT>
__global__ void __launch_bounds__(128 * (NT / 64))
gemm_mma(const __half* __restrict__ Ahi, const __half* __restrict__ Alo,
         const __half* __restrict__ Bhi, const __half* __restrict__ Blo,
         const float* __restrict__ bias,
         __half* __restrict__ Ohi, __half* __restrict__ Olo,
         float* __restrict__ Of,
         int M, int Nn, int K)
{
    extern __shared__ char smem[];
    constexpr int A_BYTES = 128 * 128;
    constexpr int B_BYTES = NT * 128;
    constexpr int STAGE   = A_BYTES + B_BYTES;

    const int tid = threadIdx.x;
    const int wid = tid >> 5;
    const int lid = tid & 31;
    const int wm  = wid & 3;
    const int wn  = wid >> 2;
    const int mBlock = blockIdx.y * 128;
    const int nBlock = blockIdx.x * NT;

    const uint32_t sbase = smem_u32(smem);

    float acc[2][8][4];
    #pragma unroll
    for (int i = 0; i < 2; i++)
        #pragma unroll
        for (int j = 0; j < 8; j++)
            #pragma unroll
            for (int q = 0; q < 4; q++) acc[i][j][q] = 0.0f;

    const int NC = (3 * K) >> 6;

    #pragma unroll
    for (int s = 0; s < STAGES - 1; s++) {
        if (s < NC)
            fill_chunk<NT>(sbase + s * STAGE, sbase + s * STAGE + A_BYTES,
                           Ahi, Alo, Bhi, Blo, s, K, M, mBlock, nBlock, tid);
        CP_COMMIT();
    }

    const int aRow  = lid & 15;
    const int aByte = (lid >> 4) << 4;
    const int bRow  = (((lid >> 4) & 1) << 3) + (lid & 7);
    const int bByte = ((lid >> 3) & 1) << 4;

    for (int c = 0; c < NC; c++) {
        const int fs = c + STAGES - 1;
        if (fs < NC) {
            const int st = fs % STAGES;
            fill_chunk<NT>(sbase + st * STAGE, sbase + st * STAGE + A_BYTES,
                           Ahi, Alo, Bhi, Blo, fs, K, M, mBlock, nBlock, tid);
        }
        CP_COMMIT();
        CP_WAIT(STAGES - 1);
        __syncthreads();

        const uint32_t stA = sbase + (c % STAGES) * STAGE;
        const uint32_t stB = stA + A_BYTES;

        #pragma unroll
        for (int s = 0; s < 4; s++) {
            uint32_t a[2][4], b[4][4];
            #pragma unroll
            for (int mi = 0; mi < 2; mi++) {
                const int row = wm * 32 + mi * 16 + aRow;
                const uint32_t off = (uint32_t)((32 * s + aByte) ^ ((row & 7) << 4));
                ldm_x4(a[mi], stA + (row << 7) + off);
            }
            #pragma unroll
            for (int g = 0; g < 4; g++) {
                const int row = wn * 64 + g * 16 + bRow;
                const uint32_t off = (uint32_t)((32 * s + bByte) ^ ((row & 7) << 4));
                ldm_x4(b[g], stB + (row << 7) + off);
            }
            #pragma unroll
            for (int mi = 0; mi < 2; mi++)
                #pragma unroll
                for (int ni = 0; ni < 8; ni++)
                    mma16816(acc[mi][ni], a[mi], b[ni >> 1][(ni & 1) * 2],
                             b[ni >> 1][(ni & 1) * 2 + 1]);
        }
        __syncthreads();
    }

    const int lid4 = lid >> 2;
    const int lq   = (lid & 3) * 2;
    #pragma unroll
    for (int mi = 0; mi < 2; mi++) {
        #pragma unroll
        for (int rr = 0; rr < 2; rr++) {
            const int row = mBlock + wm * 32 + mi * 16 + rr * 8 + lid4;
            if (row >= M) continue;
            #pragma unroll
            for (int ni = 0; ni < 8; ni++) {
                const int col = nBlock + wn * 64 + ni * 8 + lq;
                float v0 = acc[mi][ni][rr * 2 + 0] + __ldg(&bias[col]);
                float v1 = acc[mi][ni][rr * 2 + 1] + __ldg(&bias[col + 1]);
                if (TANH) { v0 = tanhf(v0); v1 = tanhf(v1); }
                if (SPLIT_OUT) {
                    __half h0 = __float2half_rn(v0), h1 = __float2half_rn(v1);
                    __half l0 = __float2half_rn(v0 - __half2float(h0));
                    __half l1 = __float2half_rn(v1 - __half2float(h1));
                    *(__half2*)(Ohi + (size_t)row * Nn + col) = __halves2half2(h0, h1);
                    *(__half2*)(Olo + (size_t)row * Nn + col) = __halves2half2(l0, l1);
                } else {
                    *(float2*)(Of + (size_t)row * Nn + col) = make_float2(v0, v1);
                }
            }
        }
    }
}

// ------------------------- CSR scatter-mean chain ---------------------------

__global__ void hist_kernel(const int* __restrict__ ei, int E)
{
    int e = blockIdx.x * blockDim.x + threadIdx.x;
    if (e < E) atomicAdd(&g_hist[ei[E + e]], 1);
}

// per-block exclusive scan of hist -> g_off (local), block totals -> g_part
__global__ void scan_local(int n)
{
    __shared__ int wsum[8];
    const int t = threadIdx.x, lane = t & 31, w = t >> 5;
    const int i = blockIdx.x * 256 + t;
    int v = (i < n) ? g_hist[i] : 0;
    int x = v;
    #pragma unroll
    for (int d = 1; d < 32; d <<= 1) {
        int y = __shfl_up_sync(0xFFFFFFFFu, x, d);
        if (lane >= d) x += y;
    }
    if (lane == 31) wsum[w] = x;
    __syncthreads();
    if (t == 0) {
        int run = 0;
        #pragma unroll
        for (int k = 0; k < 8; k++) { int tmp = wsum[k]; wsum[k] = run; run += tmp; }
        g_part[blockIdx.x] = run;
    }
    __syncthreads();
    if (i < n) g_off[i] = x - v + wsum[w];
}

__global__ void scan_top(int nb)   // single block, 512 threads
{
    __shared__ int s[512];
    const int t = threadIdx.x;
    s[t] = (t < nb) ? g_part[t] : 0;
    __syncthreads();
    #pragma unroll
    for (int d = 1; d < 512; d <<= 1) {
        int v = (t >= d) ? s[t - d] : 0;
        __syncthreads();
        s[t] += v;
        __syncthreads();
    }
    if (t < nb) g_part[t] = (t == 0) ? 0 : s[t - 1];
}

__global__ void scan_add(int n)
{
    int i = blockIdx.x * 256 + threadIdx.x;
    if (i < n) {
        int o = g_off[i] + g_part[blockIdx.x];
        g_off[i] = o;
        g_cur[i] = o;
    }
}

// compact surviving edges (gate > 0) as (src, gate)
__global__ void reorder_kernel(const int* __restrict__ ei,
                               const float* __restrict__ alpha, int E)
{
    int e = blockIdx.x * blockDim.x + threadIdx.x;
    if (e >= E) return;
    float gate = 2.0f * fmaxf(alpha[e] - 0.5f, 0.0f);
    if (gate <= 0.0f) return;
    int dst = ei[E + e];
    int pos = atomicAdd(&g_cur[dst], 1);
    g_packed[pos] = make_uint2((unsigned)ei[e], __float_as_uint(gate));
}

// warp per dst: sum gated messages, divide by full degree, write
__global__ void gather_kernel(const float* __restrict__ h,
                              float* __restrict__ out, int N)
{
    const int w    = (blockIdx.x * blockDim.x + threadIdx.x) >> 5;
    const int lane = threadIdx.x & 31;
    if (w >= N) return;
    const int start = g_off[w];
    const int end   = g_cur[w];
    const int deg   = g_hist[w];

    float4 acc = make_float4(0.f, 0.f, 0.f, 0.f);
    for (int i = start; i < end; i++) {
        uint2 p = g_packed[i];
        float g = __uint_as_float(p.y);
        float4 v = *(const float4*)(h + (size_t)p.x * 128 + lane * 4);
        acc.x += g * v.x; acc.y += g * v.y;
        acc.z += g * v.z; acc.w += g * v.w;
    }
    const float inv = 1.0f / fmaxf((float)deg, 1.0f);
    acc.x *= inv; acc.y *= inv; acc.z *= inv; acc.w *= inv;
    ((float4*)(out + (size_t)w * 128))[lane] = acc;
}

// --------------------------------- launch ----------------------------------

extern "C" void kernel_launch(void* const* d_in, const int* in_sizes, int n_in,
                              void* d_out, int out_size)
{
    const float* x     = (const float*)d_in[0];
    const float* alpha = (const float*)d_in[1];
    const int*   ei    = (const int*)  d_in[2];
    const float* W1 = (const float*)d_in[4];
    const float* b1 = (const float*)d_in[5];
    const float* W2 = (const float*)d_in[6];
    const float* b2 = (const float*)d_in[7];
    const float* W3 = (const float*)d_in[8];
    const float* b3 = (const float*)d_in[9];
    float* out = (float*)d_out;

    const int N = in_sizes[0] / 256;
    const int E = in_sizes[1];

    __half *xhi, *xlo, *h1hi, *h1lo, *h2hi, *h2lo;
    __half *w1hi, *w1lo, *w2hi, *w2lo, *w3hi, *w3lo;
    float *h;
    int *hist;
    cudaGetSymbolAddress((void**)&xhi,  g_xhi);
    cudaGetSymbolAddress((void**)&xlo,  g_xlo);
    cudaGetSymbolAddress((void**)&h1hi, g_h1hi);
    cudaGetSymbolAddress((void**)&h1lo, g_h1lo);
    cudaGetSymbolAddress((void**)&h2hi, g_h2hi);
    cudaGetSymbolAddress((void**)&h2lo, g_h2lo);
    cudaGetSymbolAddress((void**)&w1hi, g_w1hi);
    cudaGetSymbolAddress((void**)&w1lo, g_w1lo);
    cudaGetSymbolAddress((void**)&w2hi, g_w2hi);
    cudaGetSymbolAddress((void**)&w2lo, g_w2lo);
    cudaGetSymbolAddress((void**)&w3hi, g_w3hi);
    cudaGetSymbolAddress((void**)&w3lo, g_w3lo);
    cudaGetSymbolAddress((void**)&h,    g_h);
    cudaGetSymbolAddress((void**)&hist, g_hist);

    const int SMEM_256 = 4 * (128 + 256) * 128;
    const int SMEM_128 = 4 * (128 + 128) * 128;
    cudaFuncSetAttribute(gemm_mma<256, 4, true,  true >,
                         cudaFuncAttributeMaxDynamicSharedMemorySize, SMEM_256);
    cudaFuncSetAttribute(gemm_mma<128, 4, false, false>,
                         cudaFuncAttributeMaxDynamicSharedMemorySize, SMEM_128);

    // launches 1-4: splits;  launch 5: memset -> ncu (-s 5) captures gemm1
    {
        int n4 = (N * 256) / 4;
        split_kernel<<<(n4 + 255) / 256, 256>>>(x, xhi, xlo, n4);
        split_kernel<<<(512 * 256 / 4 + 255) / 256, 256>>>(W1, w1hi, w1lo, 512 * 256 / 4);
        split_kernel<<<(256 * 512 / 4 + 255) / 256, 256>>>(W2, w2hi, w2lo, 256 * 512 / 4);
        split_kernel<<<(128 * 256 / 4 + 255) / 256, 256>>>(W3, w3hi, w3lo, 128 * 256 / 4);
    }
    cudaMemsetAsync(hist, 0, (size_t)N * sizeof(int));

    const int mt = (N + 127) / 128;
    gemm_mma<256, 4, true,  true ><<<dim3(2, mt), 512, SMEM_256>>>(
        xhi, xlo, w1hi, w1lo, b1, h1hi, h1lo, nullptr, N, 512, 256);
    gemm_mma<256, 4, true,  true ><<<dim3(1, mt), 512, SMEM_256>>>(
        h1hi, h1lo, w2hi, w2lo, b2, h2hi, h2lo, nullptr, N, 256, 512);
    gemm_mma<128, 4, false, false><<<dim3(1, mt), 256, SMEM_128>>>(
        h2hi, h2lo, w3hi, w3lo, b3, nullptr, nullptr, h, N, 128, 256);

    // CSR scatter-mean
    const int nb = (N + 255) / 256;
    hist_kernel<<<(E + 255) / 256, 256>>>(ei, E);
    scan_local<<<nb, 256>>>(N);
    scan_top<<<1, 512>>>(nb);
    scan_add<<<nb, 256>>>(N);
    reorder_kernel<<<(E + 255) / 256, 256>>>(ei, alpha, E);
    gather_kernel<<<(N * 32 + 255) / 256, 256>>>(h, out, N);
}

// round 6
// speedup vs baseline: 2.0562x; 1.0495x over previous
#include <cuda_runtime.h>
#include <cuda_fp16.h>
#include <math.h>
#include <stdint.h>

// ---------------------------------------------------------------------------
// FilterGNN round 6: HMMA split-fp16 GEMMs, single-sync multistage mainloop.
// Kernel order arranged so gemm1 is the 4th kernel launch (ncu captures #4).
//   1 split_all   2 hist   3 scan_local   4 GEMM1   5 scan_top   6 scan_add
//   7 GEMM2   8 reorder   9 GEMM3   10 gather
// ---------------------------------------------------------------------------

#define MAXN 100000
#define MAXE 640000

__device__ __align__(16) __half g_xhi [MAXN * 256];
__device__ __align__(16) __half g_xlo [MAXN * 256];
__device__ __align__(16) __half g_h1hi[MAXN * 512];
__device__ __align__(16) __half g_h1lo[MAXN * 512];
__device__ __align__(16) __half g_h2hi[MAXN * 256];
__device__ __align__(16) __half g_h2lo[MAXN * 256];
__device__ __align__(16) float  g_h   [MAXN * 128];
__device__ __align__(16) __half g_w1hi[512 * 256], g_w1lo[512 * 256];
__device__ __align__(16) __half g_w2hi[256 * 512], g_w2lo[256 * 512];
__device__ __align__(16) __half g_w3hi[128 * 256], g_w3lo[128 * 256];

__device__ int   g_hist[MAXN];
__device__ int   g_off [MAXN];
__device__ int   g_cur [MAXN];
__device__ int   g_part[512];
__device__ uint2 g_packed[MAXE];

// ------------------------------- helpers -----------------------------------

__device__ __forceinline__ uint32_t smem_u32(const void* p) {
    uint32_t a;
    asm("{ .reg .u64 t; cvta.to.shared.u64 t, %1; cvt.u32.u64 %0, t; }"
        : "=r"(a) : "l"(p));
    return a;
}

#define SWZ(off) ((off) ^ (((off) >> 3) & 0x70))

__device__ __forceinline__ void cp16(uint32_t dst, const void* src) {
    asm volatile("cp.async.cg.shared.global [%0], [%1], 16;\n"
                 :: "r"(dst), "l"(src));
}
__device__ __forceinline__ void cp16z(uint32_t dst, const void* src, bool valid) {
    asm volatile("cp.async.cg.shared.global [%0], [%1], 16, %2;\n"
                 :: "r"(dst), "l"(src), "r"(valid ? 16u : 0u));
}
#define CP_COMMIT()  asm volatile("cp.async.commit_group;\n" ::: "memory")
#define CP_WAIT(n)   asm volatile("cp.async.wait_group %0;\n" :: "n"(n) : "memory")

__device__ __forceinline__ void ldm_x4(uint32_t r[4], uint32_t addr) {
    asm volatile("ldmatrix.sync.aligned.m8n8.x4.shared.b16 {%0,%1,%2,%3}, [%4];"
                 : "=r"(r[0]), "=r"(r[1]), "=r"(r[2]), "=r"(r[3]) : "r"(addr));
}

__device__ __forceinline__ void mma16816(float c[4], const uint32_t a[4],
                                         uint32_t b0, uint32_t b1) {
    asm volatile(
        "mma.sync.aligned.m16n8k16.row.col.f32.f16.f16.f32 "
        "{%0,%1,%2,%3}, {%4,%5,%6,%7}, {%8,%9}, {%0,%1,%2,%3};"
        : "+f"(c[0]), "+f"(c[1]), "+f"(c[2]), "+f"(c[3])
        : "r"(a[0]), "r"(a[1]), "r"(a[2]), "r"(a[3]), "r"(b0), "r"(b1));
}

// ------------------------------ fused split --------------------------------

__device__ __forceinline__ void split4(const float* __restrict__ a,
                                       __half* __restrict__ hi,
                                       __half* __restrict__ lo, int i)
{
    float4 v = ((const float4*)a)[i];
    float f[4] = {v.x, v.y, v.z, v.w};
    __half h[4], l[4];
    #pragma unroll
    for (int p = 0; p < 4; p++) {
        h[p] = __float2half_rn(f[p]);
        l[p] = __float2half_rn(f[p] - __half2float(h[p]));
    }
    ((uint2*)hi)[i] = *(uint2*)h;
    ((uint2*)lo)[i] = *(uint2*)l;
}

__global__ void split_all(const float* __restrict__ x,
                          const float* __restrict__ W1,
                          const float* __restrict__ W2,
                          const float* __restrict__ W3, int n4x)
{
    const int nW1 = 512 * 256 / 4, nW2 = 256 * 512 / 4, nW3 = 128 * 256 / 4;
    int i = blockIdx.x * blockDim.x + threadIdx.x;
    if (i < n4x)                        { split4(x,  g_xhi,  g_xlo,  i); return; }
    i -= n4x;
    if (i < nW1)                        { split4(W1, g_w1hi, g_w1lo, i); return; }
    i -= nW1;
    if (i < nW2)                        { split4(W2, g_w2hi, g_w2lo, i); return; }
    i -= nW2;
    if (i < nW3)                        { split4(W3, g_w3hi, g_w3lo, i); return; }
}

// --------------------------------- GEMM ------------------------------------

template<int NT>
__device__ __forceinline__ void fill_chunk(
    uint32_t sA, uint32_t sB,
    const __half* __restrict__ Ahi, const __half* __restrict__ Alo,
    const __half* __restrict__ Bhi, const __half* __restrict__ Blo,
    int c, int K, int M, int mBlock, int nBlock, int tid)
{
    constexpr int THREADS = 128 * (NT / 64);
    const int c64  = c << 6;
    const int pass = c64 / K;
    const int kk   = c64 - pass * K;
    const __half* Asrc = (pass == 1) ? Alo : Ahi;
    const __half* Bsrc = (pass == 2) ? Blo : Bhi;

    #pragma unroll
    for (int i = 0; i < 1024 / THREADS; i++) {
        int s = tid + i * THREADS;
        int row = s >> 3, byte = (s & 7) << 4;
        int grow = mBlock + row;
        bool v = grow < M;
        const char* src = (const char*)(Asrc + (size_t)(v ? grow : 0) * K + kk) + byte;
        cp16z(sA + SWZ((row << 7) + byte), src, v);
    }
    #pragma unroll
    for (int i = 0; i < (NT * 8) / THREADS; i++) {
        int s = tid + i * THREADS;
        int row = s >> 3, byte = (s & 7) << 4;
        const char* src = (const char*)(Bsrc + (size_t)(nBlock + row) * K + kk) + byte;
        cp16(sB + SWZ((row << 7) + byte), src);
    }
}

template<int NT, int STAGES, bool TANH, bool SPLIT_OUT>
__global__ void __launch_bounds__(128 * (NT / 64))
gemm_mma(const __half* __restrict__ Ahi, const __half* __restrict__ Alo,
         const __half* __restrict__ Bhi, const __half* __restrict__ Blo,
         const float* __restrict__ bias,
         __half* __restrict__ Ohi, __half* __restrict__ Olo,
         float* __restrict__ Of,
         int M, int Nn, int K)
{
    extern __shared__ char smem[];
    constexpr int A_BYTES = 128 * 128;
    constexpr int B_BYTES = NT * 128;
    constexpr int STAGE   = A_BYTES + B_BYTES;

    const int tid = threadIdx.x;
    const int wid = tid >> 5;
    const int lid = tid & 31;
    const int wm  = wid & 3;
    const int wn  = wid >> 2;
    const int mBlock = blockIdx.y * 128;
    const int nBlock = blockIdx.x * NT;

    const uint32_t sbase = smem_u32(smem);

    float acc[2][8][4];
    #pragma unroll
    for (int i = 0; i < 2; i++)
        #pragma unroll
        for (int j = 0; j < 8; j++)
            #pragma unroll
            for (int q = 0; q < 4; q++) acc[i][j][q] = 0.0f;

    const int NC = (3 * K) >> 6;

    // prologue: fill stages 0..STAGES-2, one commit group each
    #pragma unroll
    for (int s = 0; s < STAGES - 1; s++) {
        if (s < NC)
            fill_chunk<NT>(sbase + s * STAGE, sbase + s * STAGE + A_BYTES,
                           Ahi, Alo, Bhi, Blo, s, K, M, mBlock, nBlock, tid);
        CP_COMMIT();
    }

    const int aRow  = lid & 15;
    const int aByte = (lid >> 4) << 4;
    const int bRow  = (((lid >> 4) & 1) << 3) + (lid & 7);
    const int bByte = ((lid >> 3) & 1) << 4;

    // single-sync multistage mainloop
    for (int c = 0; c < NC; c++) {
        CP_WAIT(STAGES - 2);          // chunk c resident
        __syncthreads();              // all warps done with chunk c-1 stage

        const int fs = c + STAGES - 1;
        if (fs < NC) {
            const int st = fs % STAGES;   // == (c-1) % STAGES : safe after sync
            fill_chunk<NT>(sbase + st * STAGE, sbase + st * STAGE + A_BYTES,
                           Ahi, Alo, Bhi, Blo, fs, K, M, mBlock, nBlock, tid);
        }
        CP_COMMIT();

        const uint32_t stA = sbase + (c % STAGES) * STAGE;
        const uint32_t stB = stA + A_BYTES;

        #pragma unroll
        for (int s = 0; s < 4; s++) {
            uint32_t a[2][4], b[4][4];
            #pragma unroll
            for (int mi = 0; mi < 2; mi++) {
                const int row = wm * 32 + mi * 16 + aRow;
                const uint32_t off = (uint32_t)((32 * s + aByte) ^ ((row & 7) << 4));
                ldm_x4(a[mi], stA + (row << 7) + off);
            }
            #pragma unroll
            for (int g = 0; g < 4; g++) {
                const int row = wn * 64 + g * 16 + bRow;
                const uint32_t off = (uint32_t)((32 * s + bByte) ^ ((row & 7) << 4));
                ldm_x4(b[g], stB + (row << 7) + off);
            }
            #pragma unroll
            for (int mi = 0; mi < 2; mi++)
                #pragma unroll
                for (int ni = 0; ni < 8; ni++)
                    mma16816(acc[mi][ni], a[mi], b[ni >> 1][(ni & 1) * 2],
                             b[ni >> 1][(ni & 1) * 2 + 1]);
        }
    }

    const int lid4 = lid >> 2;
    const int lq   = (lid & 3) * 2;
    #pragma unroll
    for (int mi = 0; mi < 2; mi++) {
        #pragma unroll
        for (int rr = 0; rr < 2; rr++) {
            const int row = mBlock + wm * 32 + mi * 16 + rr * 8 + lid4;
            if (row >= M) continue;
            #pragma unroll
            for (int ni = 0; ni < 8; ni++) {
                const int col = nBlock + wn * 64 + ni * 8 + lq;
                float v0 = acc[mi][ni][rr * 2 + 0] + __ldg(&bias[col]);
                float v1 = acc[mi][ni][rr * 2 + 1] + __ldg(&bias[col + 1]);
                if (TANH) { v0 = tanhf(v0); v1 = tanhf(v1); }
                if (SPLIT_OUT) {
                    __half h0 = __float2half_rn(v0), h1 = __float2half_rn(v1);
                    __half l0 = __float2half_rn(v0 - __half2float(h0));
                    __half l1 = __float2half_rn(v1 - __half2float(h1));
                    *(__half2*)(Ohi + (size_t)row * Nn + col) = __halves2half2(h0, h1);
                    *(__half2*)(Olo + (size_t)row * Nn + col) = __halves2half2(l0, l1);
                } else {
                    *(float2*)(Of + (size_t)row * Nn + col) = make_float2(v0, v1);
                }
            }
        }
    }
}

// ------------------------- CSR scatter-mean chain ---------------------------

__global__ void hist_kernel(const int* __restrict__ ei, int E)
{
    int e = blockIdx.x * blockDim.x + threadIdx.x;
    if (e < E) atomicAdd(&g_hist[ei[E + e]], 1);
}

__global__ void scan_local(int n)
{
    __shared__ int wsum[8];
    const int t = threadIdx.x, lane = t & 31, w = t >> 5;
    const int i = blockIdx.x * 256 + t;
    int v = (i < n) ? g_hist[i] : 0;
    int x = v;
    #pragma unroll
    for (int d = 1; d < 32; d <<= 1) {
        int y = __shfl_up_sync(0xFFFFFFFFu, x, d);
        if (lane >= d) x += y;
    }
    if (lane == 31) wsum[w] = x;
    __syncthreads();
    if (t == 0) {
        int run = 0;
        #pragma unroll
        for (int k = 0; k < 8; k++) { int tmp = wsum[k]; wsum[k] = run; run += tmp; }
        g_part[blockIdx.x] = run;
    }
    __syncthreads();
    if (i < n) g_off[i] = x - v + wsum[w];
}

__global__ void scan_top(int nb)
{
    __shared__ int s[512];
    const int t = threadIdx.x;
    s[t] = (t < nb) ? g_part[t] : 0;
    __syncthreads();
    #pragma unroll
    for (int d = 1; d < 512; d <<= 1) {
        int v = (t >= d) ? s[t - d] : 0;
        __syncthreads();
        s[t] += v;
        __syncthreads();
    }
    if (t < nb) g_part[t] = (t == 0) ? 0 : s[t - 1];
}

__global__ void scan_add(int n)
{
    int i = blockIdx.x * 256 + threadIdx.x;
    if (i < n) {
        int o = g_off[i] + g_part[blockIdx.x];
        g_off[i] = o;
        g_cur[i] = o;
    }
}

__global__ void reorder_kernel(const int* __restrict__ ei,
                               const float* __restrict__ alpha, int E)
{
    int e = blockIdx.x * blockDim.x + threadIdx.x;
    if (e >= E) return;
    float gate = 2.0f * fmaxf(alpha[e] - 0.5f, 0.0f);
    if (gate <= 0.0f) return;
    int dst = ei[E + e];
    int pos = atomicAdd(&g_cur[dst], 1);
    g_packed[pos] = make_uint2((unsigned)ei[e], __float_as_uint(gate));
}

__global__ void gather_kernel(const float* __restrict__ h,
                              float* __restrict__ out, int N)
{
    const int w    = (blockIdx.x * blockDim.x + threadIdx.x) >> 5;
    const int lane = threadIdx.x & 31;
    if (w >= N) return;
    const int start = g_off[w];
    const int end   = g_cur[w];
    const int deg   = g_hist[w];

    float4 acc = make_float4(0.f, 0.f, 0.f, 0.f);
    for (int i = start; i < end; i++) {
        uint2 p = g_packed[i];
        float g = __uint_as_float(p.y);
        float4 v = *(const float4*)(h + (size_t)p.x * 128 + lane * 4);
        acc.x += g * v.x; acc.y += g * v.y;
        acc.z += g * v.z; acc.w += g * v.w;
    }
    const float inv = 1.0f / fmaxf((float)deg, 1.0f);
    acc.x *= inv; acc.y *= inv; acc.z *= inv; acc.w *= inv;
    ((float4*)(out + (size_t)w * 128))[lane] = acc;
}

// --------------------------------- launch ----------------------------------

extern "C" void kernel_launch(void* const* d_in, const int* in_sizes, int n_in,
                              void* d_out, int out_size)
{
    const float* x     = (const float*)d_in[0];
    const float* alpha = (const float*)d_in[1];
    const int*   ei    = (const int*)  d_in[2];
    const float* W1 = (const float*)d_in[4];
    const float* b1 = (const float*)d_in[5];
    const float* W2 = (const float*)d_in[6];
    const float* b2 = (const float*)d_in[7];
    const float* W3 = (const float*)d_in[8];
    const float* b3 = (const float*)d_in[9];
    float* out = (float*)d_out;

    const int N = in_sizes[0] / 256;
    const int E = in_sizes[1];

    __half *xhi, *xlo, *h1hi, *h1lo, *h2hi, *h2lo;
    __half *w1hi, *w1lo, *w2hi, *w2lo, *w3hi, *w3lo;
    float *h;
    int *hist;
    cudaGetSymbolAddress((void**)&xhi,  g_xhi);
    cudaGetSymbolAddress((void**)&xlo,  g_xlo);
    cudaGetSymbolAddress((void**)&h1hi, g_h1hi);
    cudaGetSymbolAddress((void**)&h1lo, g_h1lo);
    cudaGetSymbolAddress((void**)&h2hi, g_h2hi);
    cudaGetSymbolAddress((void**)&h2lo, g_h2lo);
    cudaGetSymbolAddress((void**)&w1hi, g_w1hi);
    cudaGetSymbolAddress((void**)&w1lo, g_w1lo);
    cudaGetSymbolAddress((void**)&w2hi, g_w2hi);
    cudaGetSymbolAddress((void**)&w2lo, g_w2lo);
    cudaGetSymbolAddress((void**)&w3hi, g_w3hi);
    cudaGetSymbolAddress((void**)&w3lo, g_w3lo);
    cudaGetSymbolAddress((void**)&h,    g_h);
    cudaGetSymbolAddress((void**)&hist, g_hist);

    const int SMEM_256 = 4 * (128 + 256) * 128;
    const int SMEM_128 = 4 * (128 + 128) * 128;
    cudaFuncSetAttribute(gemm_mma<256, 4, true,  true >,
                         cudaFuncAttributeMaxDynamicSharedMemorySize, SMEM_256);
    cudaFuncSetAttribute(gemm_mma<128, 4, false, false>,
                         cudaFuncAttributeMaxDynamicSharedMemorySize, SMEM_128);

    cudaMemsetAsync(hist, 0, (size_t)N * sizeof(int));

    const int mt = (N + 127) / 128;
    const int nb = (N + 255) / 256;
    const int n4x = (N * 256) / 4;
    const int splitTot = n4x + 512 * 256 / 4 + 256 * 512 / 4 + 128 * 256 / 4;

    // kernel #1
    split_all<<<(splitTot + 255) / 256, 256>>>(x, W1, W2, W3, n4x);
    // kernel #2
    hist_kernel<<<(E + 255) / 256, 256>>>(ei, E);
    // kernel #3
    scan_local<<<nb, 256>>>(N);
    // kernel #4  <-- ncu capture slot
    gemm_mma<256, 4, true,  true ><<<dim3(2, mt), 512, SMEM_256>>>(
        xhi, xlo, w1hi, w1lo, b1, h1hi, h1lo, nullptr, N, 512, 256);
    // kernel #5
    scan_top<<<1, 512>>>(nb);
    // kernel #6
    scan_add<<<nb, 256>>>(N);
    // kernel #7
    gemm_mma<256, 4, true,  true ><<<dim3(1, mt), 512, SMEM_256>>>(
        h1hi, h1lo, w2hi, w2lo, b2, h2hi, h2lo, nullptr, N, 256, 512);
    // kernel #8
    reorder_kernel<<<(E + 255) / 256, 256>>>(ei, alpha, E);
    // kernel #9
    gemm_mma<128, 4, false, false><<<dim3(1, mt), 256, SMEM_128>>>(
        h2hi, h2lo, w3hi, w3lo, b3, nullptr, nullptr, h, N, 128, 256);
    // kernel #10
    gather_kernel<<<(N * 32 + 255) / 256, 256>>>(h, out, N);
}

// round 7
// speedup vs baseline: 2.9054x; 1.4130x over previous
#include <cuda_runtime.h>
#include <cuda_fp16.h>
#include <math.h>
#include <stdint.h>

// ---------------------------------------------------------------------------
// FilterGNN round 7: 2-term split GEMM, B shared across A-passes.
//   D = (Ah + Al) @ Bh^T ; Bh = fp16(W) (weights rounded once)
//   per K-chunk stage holds {Ah, Al, B}; both passes reuse the same B frags.
// Kernel order keeps gemm1 as launch #4 (ncu capture slot).
// ---------------------------------------------------------------------------

#define MAXN 100000
#define MAXE 640000

__device__ __align__(16) __half g_xhi [MAXN * 256];
__device__ __align__(16) __half g_xlo [MAXN * 256];
__device__ __align__(16) __half g_h1hi[MAXN * 512];
__device__ __align__(16) __half g_h1lo[MAXN * 512];
__device__ __align__(16) __half g_h2hi[MAXN * 256];
__device__ __align__(16) __half g_h2lo[MAXN * 256];
__device__ __align__(16) float  g_h   [MAXN * 128];
__device__ __align__(16) __half g_w1h[512 * 256];
__device__ __align__(16) __half g_w2h[256 * 512];
__device__ __align__(16) __half g_w3h[128 * 256];

__device__ int   g_hist[MAXN];
__device__ int   g_off [MAXN];
__device__ int   g_cur [MAXN];
__device__ int   g_part[512];
__device__ uint2 g_packed[MAXE];

// ------------------------------- helpers -----------------------------------

__device__ __forceinline__ uint32_t smem_u32(const void* p) {
    uint32_t a;
    asm("{ .reg .u64 t; cvta.to.shared.u64 t, %1; cvt.u32.u64 %0, t; }"
        : "=r"(a) : "l"(p));
    return a;
}

#define SWZ(off) ((off) ^ (((off) >> 3) & 0x70))

__device__ __forceinline__ void cp16(uint32_t dst, const void* src) {
    asm volatile("cp.async.cg.shared.global [%0], [%1], 16;\n"
                 :: "r"(dst), "l"(src));
}
__device__ __forceinline__ void cp16z(uint32_t dst, const void* src, bool valid) {
    asm volatile("cp.async.cg.shared.global [%0], [%1], 16, %2;\n"
                 :: "r"(dst), "l"(src), "r"(valid ? 16u : 0u));
}
#define CP_COMMIT()  asm volatile("cp.async.commit_group;\n" ::: "memory")
#define CP_WAIT(n)   asm volatile("cp.async.wait_group %0;\n" :: "n"(n) : "memory")

__device__ __forceinline__ void ldm_x4(uint32_t r[4], uint32_t addr) {
    asm volatile("ldmatrix.sync.aligned.m8n8.x4.shared.b16 {%0,%1,%2,%3}, [%4];"
                 : "=r"(r[0]), "=r"(r[1]), "=r"(r[2]), "=r"(r[3]) : "r"(addr));
}

__device__ __forceinline__ void mma16816(float c[4], const uint32_t a[4],
                                         uint32_t b0, uint32_t b1) {
    asm volatile(
        "mma.sync.aligned.m16n8k16.row.col.f32.f16.f16.f32 "
        "{%0,%1,%2,%3}, {%4,%5,%6,%7}, {%8,%9}, {%0,%1,%2,%3};"
        : "+f"(c[0]), "+f"(c[1]), "+f"(c[2]), "+f"(c[3])
        : "r"(a[0]), "r"(a[1]), "r"(a[2]), "r"(a[3]), "r"(b0), "r"(b1));
}

// ------------------------------ fused split --------------------------------
// x -> hi+lo fp16; weights -> single-rounded fp16.

__device__ __forceinline__ void split4(const float* __restrict__ a,
                                       __half* __restrict__ hi,
                                       __half* __restrict__ lo, int i)
{
    float4 v = ((const float4*)a)[i];
    float f[4] = {v.x, v.y, v.z, v.w};
    __half h[4], l[4];
    #pragma unroll
    for (int p = 0; p < 4; p++) {
        h[p] = __float2half_rn(f[p]);
        l[p] = __float2half_rn(f[p] - __half2float(h[p]));
    }
    ((uint2*)hi)[i] = *(uint2*)h;
    ((uint2*)lo)[i] = *(uint2*)l;
}

__device__ __forceinline__ void round4(const float* __restrict__ a,
                                       __half* __restrict__ hi, int i)
{
    float4 v = ((const float4*)a)[i];
    __half h[4] = { __float2half_rn(v.x), __float2half_rn(v.y),
                    __float2half_rn(v.z), __float2half_rn(v.w) };
    ((uint2*)hi)[i] = *(uint2*)h;
}

__global__ void split_all(const float* __restrict__ x,
                          const float* __restrict__ W1,
                          const float* __restrict__ W2,
                          const float* __restrict__ W3, int n4x)
{
    const int nW1 = 512 * 256 / 4, nW2 = 256 * 512 / 4, nW3 = 128 * 256 / 4;
    int i = blockIdx.x * blockDim.x + threadIdx.x;
    if (i < n4x) { split4(x, g_xhi, g_xlo, i); return; }
    i -= n4x;
    if (i < nW1) { round4(W1, g_w1h, i); return; }
    i -= nW1;
    if (i < nW2) { round4(W2, g_w2h, i); return; }
    i -= nW2;
    if (i < nW3) { round4(W3, g_w3h, i); return; }
}

// --------------------------------- GEMM ------------------------------------
// C[128 x NT] tile; K in 64-col chunks. Stage = {Ah 16K | Al 16K | B NT*128}.
// Both A-passes run against the same resident B chunk.

template<int NT>
__device__ __forceinline__ void fill_chunk(
    uint32_t sAh, uint32_t sAl, uint32_t sB,
    const __half* __restrict__ Ahi, const __half* __restrict__ Alo,
    const __half* __restrict__ Bh,
    int c, int K, int M, int mBlock, int nBlock, int tid)
{
    constexpr int THREADS = 128 * (NT / 64);
    const int kk = c << 6;

    #pragma unroll
    for (int i = 0; i < 1024 / THREADS; i++) {      // A hi+lo: 128 rows x 128B
        int s = tid + i * THREADS;
        int row = s >> 3, byte = (s & 7) << 4;
        int grow = mBlock + row;
        bool v = grow < M;
        size_t base = (size_t)(v ? grow : 0) * K + kk;
        uint32_t soff = SWZ((row << 7) + byte);
        cp16z(sAh + soff, (const char*)(Ahi + base) + byte, v);
        cp16z(sAl + soff, (const char*)(Alo + base) + byte, v);
    }
    #pragma unroll
    for (int i = 0; i < (NT * 8) / THREADS; i++) {  // B: NT rows x 128B
        int s = tid + i * THREADS;
        int row = s >> 3, byte = (s & 7) << 4;
        const char* src = (const char*)(Bh + (size_t)(nBlock + row) * K + kk) + byte;
        cp16(sB + SWZ((row << 7) + byte), src);
    }
}

template<int NT, int STAGES, bool TANH, bool SPLIT_OUT>
__global__ void __launch_bounds__(128 * (NT / 64))
gemm_mma(const __half* __restrict__ Ahi, const __half* __restrict__ Alo,
         const __half* __restrict__ Bh,
         const float* __restrict__ bias,
         __half* __restrict__ Ohi, __half* __restrict__ Olo,
         float* __restrict__ Of,
         int M, int Nn, int K)
{
    extern __shared__ char smem[];
    constexpr int A_BYTES = 128 * 128;              // one A part (hi or lo)
    constexpr int B_BYTES = NT * 128;
    constexpr int STAGE   = 2 * A_BYTES + B_BYTES;

    const int tid = threadIdx.x;
    const int wid = tid >> 5;
    const int lid = tid & 31;
    const int wm  = wid & 3;
    const int wn  = wid >> 2;
    const int mBlock = blockIdx.y * 128;
    const int nBlock = blockIdx.x * NT;

    const uint32_t sbase = smem_u32(smem);

    float acc[2][8][4];
    #pragma unroll
    for (int i = 0; i < 2; i++)
        #pragma unroll
        for (int j = 0; j < 8; j++)
            #pragma unroll
            for (int q = 0; q < 4; q++) acc[i][j][q] = 0.0f;

    const int NC = K >> 6;

    #pragma unroll
    for (int s = 0; s < STAGES - 1; s++) {
        if (s < NC) {
            uint32_t st = sbase + s * STAGE;
            fill_chunk<NT>(st, st + A_BYTES, st + 2 * A_BYTES,
                           Ahi, Alo, Bh, s, K, M, mBlock, nBlock, tid);
        }
        CP_COMMIT();
    }

    const int aRow  = lid & 15;
    const int aByte = (lid >> 4) << 4;
    const int bRow  = (((lid >> 4) & 1) << 3) + (lid & 7);
    const int bByte = ((lid >> 3) & 1) << 4;

    for (int c = 0; c < NC; c++) {
        CP_WAIT(STAGES - 2);
        __syncthreads();

        const int fs = c + STAGES - 1;
        if (fs < NC) {
            uint32_t st = sbase + (fs % STAGES) * STAGE;
            fill_chunk<NT>(st, st + A_BYTES, st + 2 * A_BYTES,
                           Ahi, Alo, Bh, fs, K, M, mBlock, nBlock, tid);
        }
        CP_COMMIT();

        const uint32_t stAh = sbase + (c % STAGES) * STAGE;
        const uint32_t stAl = stAh + A_BYTES;
        const uint32_t stB  = stAh + 2 * A_BYTES;

        #pragma unroll
        for (int s = 0; s < 4; s++) {               // 4 x k16 per 64-col chunk
            uint32_t ah[2][4], al[2][4], b[4][4];
            #pragma unroll
            for (int mi = 0; mi < 2; mi++) {
                const int row = wm * 32 + mi * 16 + aRow;
                const uint32_t off = (uint32_t)((32 * s + aByte) ^ ((row & 7) << 4));
                ldm_x4(ah[mi], stAh + (row << 7) + off);
                ldm_x4(al[mi], stAl + (row << 7) + off);
            }
            #pragma unroll
            for (int g = 0; g < 4; g++) {
                const int row = wn * 64 + g * 16 + bRow;
                const uint32_t off = (uint32_t)((32 * s + bByte) ^ ((row & 7) << 4));
                ldm_x4(b[g], stB + (row << 7) + off);
            }
            #pragma unroll
            for (int mi = 0; mi < 2; mi++)
                #pragma unroll
                for (int ni = 0; ni < 8; ni++) {
                    mma16816(acc[mi][ni], ah[mi], b[ni >> 1][(ni & 1) * 2],
                             b[ni >> 1][(ni & 1) * 2 + 1]);
                    mma16816(acc[mi][ni], al[mi], b[ni >> 1][(ni & 1) * 2],
                             b[ni >> 1][(ni & 1) * 2 + 1]);
                }
        }
    }

    const int lid4 = lid >> 2;
    const int lq   = (lid & 3) * 2;
    #pragma unroll
    for (int mi = 0; mi < 2; mi++) {
        #pragma unroll
        for (int rr = 0; rr < 2; rr++) {
            const int row = mBlock + wm * 32 + mi * 16 + rr * 8 + lid4;
            if (row >= M) continue;
            #pragma unroll
            for (int ni = 0; ni < 8; ni++) {
                const int col = nBlock + wn * 64 + ni * 8 + lq;
                float v0 = acc[mi][ni][rr * 2 + 0] + __ldg(&bias[col]);
                float v1 = acc[mi][ni][rr * 2 + 1] + __ldg(&bias[col + 1]);
                if (TANH) { v0 = tanhf(v0); v1 = tanhf(v1); }
                if (SPLIT_OUT) {
                    __half h0 = __float2half_rn(v0), h1 = __float2half_rn(v1);
                    __half l0 = __float2half_rn(v0 - __half2float(h0));
                    __half l1 = __float2half_rn(v1 - __half2float(h1));
                    *(__half2*)(Ohi + (size_t)row * Nn + col) = __halves2half2(h0, h1);
                    *(__half2*)(Olo + (size_t)row * Nn + col) = __halves2half2(l0, l1);
                } else {
                    *(float2*)(Of + (size_t)row * Nn + col) = make_float2(v0, v1);
                }
            }
        }
    }
}

// ------------------------- CSR scatter-mean chain ---------------------------

__global__ void hist_kernel(const int* __restrict__ ei, int E)
{
    int e = blockIdx.x * blockDim.x + threadIdx.x;
    if (e < E) atomicAdd(&g_hist[ei[E + e]], 1);
}

__global__ void scan_local(int n)
{
    __shared__ int wsum[8];
    const int t = threadIdx.x, lane = t & 31, w = t >> 5;
    const int i = blockIdx.x * 256 + t;
    int v = (i < n) ? g_hist[i] : 0;
    int x = v;
    #pragma unroll
    for (int d = 1; d < 32; d <<= 1) {
        int y = __shfl_up_sync(0xFFFFFFFFu, x, d);
        if (lane >= d) x += y;
    }
    if (lane == 31) wsum[w] = x;
    __syncthreads();
    if (t == 0) {
        int run = 0;
        #pragma unroll
        for (int k = 0; k < 8; k++) { int tmp = wsum[k]; wsum[k] = run; run += tmp; }
        g_part[blockIdx.x] = run;
    }
    __syncthreads();
    if (i < n) g_off[i] = x - v + wsum[w];
}

__global__ void scan_top(int nb)
{
    __shared__ int s[512];
    const int t = threadIdx.x;
    s[t] = (t < nb) ? g_part[t] : 0;
    __syncthreads();
    #pragma unroll
    for (int d = 1; d < 512; d <<= 1) {
        int v = (t >= d) ? s[t - d] : 0;
        __syncthreads();
        s[t] += v;
        __syncthreads();
    }
    if (t < nb) g_part[t] = (t == 0) ? 0 : s[t - 1];
}

__global__ void scan_add(int n)
{
    int i = blockIdx.x * 256 + threadIdx.x;
    if (i < n) {
        int o = g_off[i] + g_part[blockIdx.x];
        g_off[i] = o;
        g_cur[i] = o;
    }
}

__global__ void reorder_kernel(const int* __restrict__ ei,
                               const float* __restrict__ alpha, int E)
{
    int e = blockIdx.x * blockDim.x + threadIdx.x;
    if (e >= E) return;
    float gate = 2.0f * fmaxf(alpha[e] - 0.5f, 0.0f);
    if (gate <= 0.0f) return;
    int dst = ei[E + e];
    int pos = atomicAdd(&g_cur[dst], 1);
    g_packed[pos] = make_uint2((unsigned)ei[e], __float_as_uint(gate));
}

__global__ void gather_kernel(const float* __restrict__ h,
                              float* __restrict__ out, int N)
{
    const int w    = (blockIdx.x * blockDim.x + threadIdx.x) >> 5;
    const int lane = threadIdx.x & 31;
    if (w >= N) return;
    const int start = g_off[w];
    const int end   = g_cur[w];
    const int deg   = g_hist[w];

    float4 acc = make_float4(0.f, 0.f, 0.f, 0.f);
    for (int i = start; i < end; i++) {
        uint2 p = g_packed[i];
        float g = __uint_as_float(p.y);
        float4 v = *(const float4*)(h + (size_t)p.x * 128 + lane * 4);
        acc.x += g * v.x; acc.y += g * v.y;
        acc.z += g * v.z; acc.w += g * v.w;
    }
    const float inv = 1.0f / fmaxf((float)deg, 1.0f);
    acc.x *= inv; acc.y *= inv; acc.z *= inv; acc.w *= inv;
    ((float4*)(out + (size_t)w * 128))[lane] = acc;
}

// --------------------------------- launch ----------------------------------

extern "C" void kernel_launch(void* const* d_in, const int* in_sizes, int n_in,
                              void* d_out, int out_size)
{
    const float* x     = (const float*)d_in[0];
    const float* alpha = (const float*)d_in[1];
    const int*   ei    = (const int*)  d_in[2];
    const float* W1 = (const float*)d_in[4];
    const float* b1 = (const float*)d_in[5];
    const float* W2 = (const float*)d_in[6];
    const float* b2 = (const float*)d_in[7];
    const float* W3 = (const float*)d_in[8];
    const float* b3 = (const float*)d_in[9];
    float* out = (float*)d_out;

    const int N = in_sizes[0] / 256;
    const int E = in_sizes[1];

    __half *xhi, *xlo, *h1hi, *h1lo, *h2hi, *h2lo;
    __half *w1h, *w2h, *w3h;
    float *h;
    int *hist;
    cudaGetSymbolAddress((void**)&xhi,  g_xhi);
    cudaGetSymbolAddress((void**)&xlo,  g_xlo);
    cudaGetSymbolAddress((void**)&h1hi, g_h1hi);
    cudaGetSymbolAddress((void**)&h1lo, g_h1lo);
    cudaGetSymbolAddress((void**)&h2hi, g_h2hi);
    cudaGetSymbolAddress((void**)&h2lo, g_h2lo);
    cudaGetSymbolAddress((void**)&w1h,  g_w1h);
    cudaGetSymbolAddress((void**)&w2h,  g_w2h);
    cudaGetSymbolAddress((void**)&w3h,  g_w3h);
    cudaGetSymbolAddress((void**)&h,    g_h);
    cudaGetSymbolAddress((void**)&hist, g_hist);

    // smem: STAGES * (2*16384 + NT*128)
    const int SMEM_256 = 3 * (2 * 16384 + 256 * 128);   // 196608
    const int SMEM_128 = 3 * (2 * 16384 + 128 * 128);   // 147456
    cudaFuncSetAttribute(gemm_mma<256, 3, true,  true >,
                         cudaFuncAttributeMaxDynamicSharedMemorySize, SMEM_256);
    cudaFuncSetAttribute(gemm_mma<128, 3, false, false>,
                         cudaFuncAttributeMaxDynamicSharedMemorySize, SMEM_128);

    cudaMemsetAsync(hist, 0, (size_t)N * sizeof(int));

    const int mt = (N + 127) / 128;
    const int nb = (N + 255) / 256;
    const int n4x = (N * 256) / 4;
    const int splitTot = n4x + 512 * 256 / 4 + 256 * 512 / 4 + 128 * 256 / 4;

    // kernel #1
    split_all<<<(splitTot + 255) / 256, 256>>>(x, W1, W2, W3, n4x);
    // kernel #2
    hist_kernel<<<(E + 255) / 256, 256>>>(ei, E);
    // kernel #3
    scan_local<<<nb, 256>>>(N);
    // kernel #4  <-- ncu capture slot
    gemm_mma<256, 3, true,  true ><<<dim3(2, mt), 512, SMEM_256>>>(
        xhi, xlo, w1h, b1, h1hi, h1lo, nullptr, N, 512, 256);
    // kernel #5
    scan_top<<<1, 512>>>(nb);
    // kernel #6
    scan_add<<<nb, 256>>>(N);
    // kernel #7
    gemm_mma<256, 3, true,  true ><<<dim3(1, mt), 512, SMEM_256>>>(
        h1hi, h1lo, w2h, b2, h2hi, h2lo, nullptr, N, 256, 512);
    // kernel #8
    reorder_kernel<<<(E + 255) / 256, 256>>>(ei, alpha, E);
    // kernel #9
    gemm_mma<128, 3, false, false><<<dim3(1, mt), 256, SMEM_128>>>(
        h2hi, h2lo, w3h, b3, nullptr, nullptr, h, N, 128, 256);
    // kernel #10
    gather_kernel<<<(N * 32 + 255) / 256, 256>>>(h, out, N);
}

// round 8
// speedup vs baseline: 2.9276x; 1.0077x over previous
#include <cuda_runtime.h>
#include <cuda_fp16.h>
#include <math.h>
#include <stdint.h>

// ---------------------------------------------------------------------------
// FilterGNN round 8: 2-term split GEMM + warp-staggered k-steps + frag pipeline.
//   D = (Ah + Al) @ fp16(W)^T ; per chunk both passes reuse resident B.
//   Warps rotate k16-step order (de-phased LDSM/MMA) and double-buffer ah.
// Kernel order keeps gemm1 as launch #4 (ncu capture slot).
// ---------------------------------------------------------------------------

#define MAXN 100000
#define MAXE 640000

__device__ __align__(16) __half g_xhi [MAXN * 256];
__device__ __align__(16) __half g_xlo [MAXN * 256];
__device__ __align__(16) __half g_h1hi[MAXN * 512];
__device__ __align__(16) __half g_h1lo[MAXN * 512];
__device__ __align__(16) __half g_h2hi[MAXN * 256];
__device__ __align__(16) __half g_h2lo[MAXN * 256];
__device__ __align__(16) float  g_h   [MAXN * 128];
__device__ __align__(16) __half g_w1h[512 * 256];
__device__ __align__(16) __half g_w2h[256 * 512];
__device__ __align__(16) __half g_w3h[128 * 256];

__device__ int   g_hist[MAXN];
__device__ int   g_off [MAXN];
__device__ int   g_cur [MAXN];
__device__ int   g_part[512];
__device__ uint2 g_packed[MAXE];

// ------------------------------- helpers -----------------------------------

__device__ __forceinline__ uint32_t smem_u32(const void* p) {
    uint32_t a;
    asm("{ .reg .u64 t; cvta.to.shared.u64 t, %1; cvt.u32.u64 %0, t; }"
        : "=r"(a) : "l"(p));
    return a;
}

#define SWZ(off) ((off) ^ (((off) >> 3) & 0x70))

__device__ __forceinline__ void cp16(uint32_t dst, const void* src) {
    asm volatile("cp.async.cg.shared.global [%0], [%1], 16;\n"
                 :: "r"(dst), "l"(src));
}
__device__ __forceinline__ void cp16z(uint32_t dst, const void* src, bool valid) {
    asm volatile("cp.async.cg.shared.global [%0], [%1], 16, %2;\n"
                 :: "r"(dst), "l"(src), "r"(valid ? 16u : 0u));
}
#define CP_COMMIT()  asm volatile("cp.async.commit_group;\n" ::: "memory")
#define CP_WAIT(n)   asm volatile("cp.async.wait_group %0;\n" :: "n"(n) : "memory")

__device__ __forceinline__ void ldm_x4(uint32_t r[4], uint32_t addr) {
    asm volatile("ldmatrix.sync.aligned.m8n8.x4.shared.b16 {%0,%1,%2,%3}, [%4];"
                 : "=r"(r[0]), "=r"(r[1]), "=r"(r[2]), "=r"(r[3]) : "r"(addr));
}

__device__ __forceinline__ void mma16816(float c[4], const uint32_t a[4],
                                         uint32_t b0, uint32_t b1) {
    asm volatile(
        "mma.sync.aligned.m16n8k16.row.col.f32.f16.f16.f32 "
        "{%0,%1,%2,%3}, {%4,%5,%6,%7}, {%8,%9}, {%0,%1,%2,%3};"
        : "+f"(c[0]), "+f"(c[1]), "+f"(c[2]), "+f"(c[3])
        : "r"(a[0]), "r"(a[1]), "r"(a[2]), "r"(a[3]), "r"(b0), "r"(b1));
}

// ------------------------------ fused split --------------------------------

__device__ __forceinline__ void split4(const float* __restrict__ a,
                                       __half* __restrict__ hi,
                                       __half* __restrict__ lo, int i)
{
    float4 v = ((const float4*)a)[i];
    float f[4] = {v.x, v.y, v.z, v.w};
    __half h[4], l[4];
    #pragma unroll
    for (int p = 0; p < 4; p++) {
        h[p] = __float2half_rn(f[p]);
        l[p] = __float2half_rn(f[p] - __half2float(h[p]));
    }
    ((uint2*)hi)[i] = *(uint2*)h;
    ((uint2*)lo)[i] = *(uint2*)l;
}

__device__ __forceinline__ void round4(const float* __restrict__ a,
                                       __half* __restrict__ hi, int i)
{
    float4 v = ((const float4*)a)[i];
    __half h[4] = { __float2half_rn(v.x), __float2half_rn(v.y),
                    __float2half_rn(v.z), __float2half_rn(v.w) };
    ((uint2*)hi)[i] = *(uint2*)h;
}

__global__ void split_all(const float* __restrict__ x,
                          const float* __restrict__ W1,
                          const float* __restrict__ W2,
                          const float* __restrict__ W3, int n4x)
{
    const int nW1 = 512 * 256 / 4, nW2 = 256 * 512 / 4, nW3 = 128 * 256 / 4;
    int i = blockIdx.x * blockDim.x + threadIdx.x;
    if (i < n4x) { split4(x, g_xhi, g_xlo, i); return; }
    i -= n4x;
    if (i < nW1) { round4(W1, g_w1h, i); return; }
    i -= nW1;
    if (i < nW2) { round4(W2, g_w2h, i); return; }
    i -= nW2;
    if (i < nW3) { round4(W3, g_w3h, i); return; }
}

// --------------------------------- GEMM ------------------------------------

template<int NT>
__device__ __forceinline__ void fill_chunk(
    uint32_t sAh, uint32_t sAl, uint32_t sB,
    const __half* __restrict__ Ahi, const __half* __restrict__ Alo,
    const __half* __restrict__ Bh,
    int c, int K, int M, int mBlock, int nBlock, int tid)
{
    constexpr int THREADS = 128 * (NT / 64);
    const int kk = c << 6;

    #pragma unroll
    for (int i = 0; i < 1024 / THREADS; i++) {
        int s = tid + i * THREADS;
        int row = s >> 3, byte = (s & 7) << 4;
        int grow = mBlock + row;
        bool v = grow < M;
        size_t base = (size_t)(v ? grow : 0) * K + kk;
        uint32_t soff = SWZ((row << 7) + byte);
        cp16z(sAh + soff, (const char*)(Ahi + base) + byte, v);
        cp16z(sAl + soff, (const char*)(Alo + base) + byte, v);
    }
    #pragma unroll
    for (int i = 0; i < (NT * 8) / THREADS; i++) {
        int s = tid + i * THREADS;
        int row = s >> 3, byte = (s & 7) << 4;
        const char* src = (const char*)(Bh + (size_t)(nBlock + row) * K + kk) + byte;
        cp16(sB + SWZ((row << 7) + byte), src);
    }
}

template<int NT, int STAGES, bool TANH, bool SPLIT_OUT>
__global__ void __launch_bounds__(128 * (NT / 64))
gemm_mma(const __half* __restrict__ Ahi, const __half* __restrict__ Alo,
         const __half* __restrict__ Bh,
         const float* __restrict__ bias,
         __half* __restrict__ Ohi, __half* __restrict__ Olo,
         float* __restrict__ Of,
         int M, int Nn, int K)
{
    extern __shared__ char smem[];
    constexpr int A_BYTES = 128 * 128;
    constexpr int B_BYTES = NT * 128;
    constexpr int STAGE   = 2 * A_BYTES + B_BYTES;

    const int tid = threadIdx.x;
    const int wid = tid >> 5;
    const int lid = tid & 31;
    const int wm  = wid & 3;
    const int wn  = wid >> 2;
    const int sb  = wid & 3;            // per-warp k-step stagger
    const int mBlock = blockIdx.y * 128;
    const int nBlock = blockIdx.x * NT;

    const uint32_t sbase = smem_u32(smem);

    float acc[2][8][4];
    #pragma unroll
    for (int i = 0; i < 2; i++)
        #pragma unroll
        for (int j = 0; j < 8; j++)
            #pragma unroll
            for (int q = 0; q < 4; q++) acc[i][j][q] = 0.0f;

    const int NC = K >> 6;

    #pragma unroll
    for (int s = 0; s < STAGES - 1; s++) {
        if (s < NC) {
            uint32_t st = sbase + s * STAGE;
            fill_chunk<NT>(st, st + A_BYTES, st + 2 * A_BYTES,
                           Ahi, Alo, Bh, s, K, M, mBlock, nBlock, tid);
        }
        CP_COMMIT();
    }

    const int aRow  = lid & 15;
    const int aByte = (lid >> 4) << 4;
    const int bRow  = (((lid >> 4) & 1) << 3) + (lid & 7);
    const int bByte = ((lid >> 3) & 1) << 4;

    // lane-constant pieces of the ldmatrix addresses
    const uint32_t aOffBase[2] = {
        (uint32_t)(((wm * 32 +  0 + aRow) << 7)),
        (uint32_t)(((wm * 32 + 16 + aRow) << 7)) };
    const uint32_t aSwz = ((aRow & 7) << 4);
    const uint32_t bOffBase[4] = {
        (uint32_t)(((wn * 64 +  0 + bRow) << 7)),
        (uint32_t)(((wn * 64 + 16 + bRow) << 7)),
        (uint32_t)(((wn * 64 + 32 + bRow) << 7)),
        (uint32_t)(((wn * 64 + 48 + bRow) << 7)) };
    const uint32_t bSwz = ((bRow & 7) << 4);

    for (int c = 0; c < NC; c++) {
        CP_WAIT(STAGES - 2);
        __syncthreads();

        const int fs = c + STAGES - 1;
        if (fs < NC) {
            uint32_t st = sbase + (fs % STAGES) * STAGE;
            fill_chunk<NT>(st, st + A_BYTES, st + 2 * A_BYTES,
                           Ahi, Alo, Bh, fs, K, M, mBlock, nBlock, tid);
        }
        CP_COMMIT();

        const uint32_t stAh = sbase + (c % STAGES) * STAGE;
        const uint32_t stAl = stAh + A_BYTES;
        const uint32_t stB  = stAh + 2 * A_BYTES;

        uint32_t ah[2][2][4];       // double-buffered ah frags
        {
            const uint32_t off0 = (uint32_t)((32 * sb + aByte)) ^ aSwz;
            ldm_x4(ah[0][0], stAh + aOffBase[0] + off0);
            ldm_x4(ah[0][1], stAh + aOffBase[1] + off0);
        }

        #pragma unroll
        for (int ss = 0; ss < 4; ss++) {
            const int s   = (ss + sb) & 3;
            const int cur = ss & 1, nxt = cur ^ 1;

            uint32_t b[4][4], al[2][4];
            const uint32_t offB = (uint32_t)((32 * s + bByte)) ^ bSwz;
            #pragma unroll
            for (int g = 0; g < 4; g++)
                ldm_x4(b[g], stB + bOffBase[g] + offB);
            const uint32_t offA = (uint32_t)((32 * s + aByte)) ^ aSwz;
            ldm_x4(al[0], stAl + aOffBase[0] + offA);
            ldm_x4(al[1], stAl + aOffBase[1] + offA);

            // hi MMAs, mi = 0
            #pragma unroll
            for (int ni = 0; ni < 8; ni++)
                mma16816(acc[0][ni], ah[cur][0], b[ni >> 1][(ni & 1) * 2],
                         b[ni >> 1][(ni & 1) * 2 + 1]);

            // prefetch next step's ah while tensor pipe is busy
            if (ss < 3) {
                const int s2 = (ss + 1 + sb) & 3;
                const uint32_t offN = (uint32_t)((32 * s2 + aByte)) ^ aSwz;
                ldm_x4(ah[nxt][0], stAh + aOffBase[0] + offN);
                ldm_x4(ah[nxt][1], stAh + aOffBase[1] + offN);
            }

            // hi MMAs, mi = 1
            #pragma unroll
            for (int ni = 0; ni < 8; ni++)
                mma16816(acc[1][ni], ah[cur][1], b[ni >> 1][(ni & 1) * 2],
                         b[ni >> 1][(ni & 1) * 2 + 1]);

            // lo MMAs
            #pragma unroll
            for (int mi = 0; mi < 2; mi++)
                #pragma unroll
                for (int ni = 0; ni < 8; ni++)
                    mma16816(acc[mi][ni], al[mi], b[ni >> 1][(ni & 1) * 2],
                             b[ni >> 1][(ni & 1) * 2 + 1]);
        }
    }

    const int lid4 = lid >> 2;
    const int lq   = (lid & 3) * 2;
    #pragma unroll
    for (int mi = 0; mi < 2; mi++) {
        #pragma unroll
        for (int rr = 0; rr < 2; rr++) {
            const int row = mBlock + wm * 32 + mi * 16 + rr * 8 + lid4;
            if (row >= M) continue;
            #pragma unroll
            for (int ni = 0; ni < 8; ni++) {
                const int col = nBlock + wn * 64 + ni * 8 + lq;
                float v0 = acc[mi][ni][rr * 2 + 0] + __ldg(&bias[col]);
                float v1 = acc[mi][ni][rr * 2 + 1] + __ldg(&bias[col + 1]);
                if (TANH) { v0 = tanhf(v0); v1 = tanhf(v1); }
                if (SPLIT_OUT) {
                    __half h0 = __float2half_rn(v0), h1 = __float2half_rn(v1);
                    __half l0 = __float2half_rn(v0 - __half2float(h0));
                    __half l1 = __float2half_rn(v1 - __half2float(h1));
                    *(__half2*)(Ohi + (size_t)row * Nn + col) = __halves2half2(h0, h1);
                    *(__half2*)(Olo + (size_t)row * Nn + col) = __halves2half2(l0, l1);
                } else {
                    *(float2*)(Of + (size_t)row * Nn + col) = make_float2(v0, v1);
                }
            }
        }
    }
}

// ------------------------- CSR scatter-mean chain ---------------------------

__global__ void hist_kernel(const int* __restrict__ ei, int E)
{
    int e = blockIdx.x * blockDim.x + threadIdx.x;
    if (e < E) atomicAdd(&g_hist[ei[E + e]], 1);
}

__global__ void scan_local(int n)
{
    __shared__ int wsum[8];
    const int t = threadIdx.x, lane = t & 31, w = t >> 5;
    const int i = blockIdx.x * 256 + t;
    int v = (i < n) ? g_hist[i] : 0;
    int x = v;
    #pragma unroll
    for (int d = 1; d < 32; d <<= 1) {
        int y = __shfl_up_sync(0xFFFFFFFFu, x, d);
        if (lane >= d) x += y;
    }
    if (lane == 31) wsum[w] = x;
    __syncthreads();
    if (t == 0) {
        int run = 0;
        #pragma unroll
        for (int k = 0; k < 8; k++) { int tmp = wsum[k]; wsum[k] = run; run += tmp; }
        g_part[blockIdx.x] = run;
    }
    __syncthreads();
    if (i < n) g_off[i] = x - v + wsum[w];
}

__global__ void scan_top(int nb)
{
    __shared__ int s[512];
    const int t = threadIdx.x;
    s[t] = (t < nb) ? g_part[t] : 0;
    __syncthreads();
    #pragma unroll
    for (int d = 1; d < 512; d <<= 1) {
        int v = (t >= d) ? s[t - d] : 0;
        __syncthreads();
        s[t] += v;
        __syncthreads();
    }
    if (t < nb) g_part[t] = (t == 0) ? 0 : s[t - 1];
}

__global__ void scan_add(int n)
{
    int i = blockIdx.x * 256 + threadIdx.x;
    if (i < n) {
        int o = g_off[i] + g_part[blockIdx.x];
        g_off[i] = o;
        g_cur[i] = o;
    }
}

__global__ void reorder_kernel(const int* __restrict__ ei,
                               const float* __restrict__ alpha, int E)
{
    int e = blockIdx.x * blockDim.x + threadIdx.x;
    if (e >= E) return;
    float gate = 2.0f * fmaxf(alpha[e] - 0.5f, 0.0f);
    if (gate <= 0.0f) return;
    int dst = ei[E + e];
    int pos = atomicAdd(&g_cur[dst], 1);
    g_packed[pos] = make_uint2((unsigned)ei[e], __float_as_uint(gate));
}

__global__ void gather_kernel(const float* __restrict__ h,
                              float* __restrict__ out, int N)
{
    const int w    = (blockIdx.x * blockDim.x + threadIdx.x) >> 5;
    const int lane = threadIdx.x & 31;
    if (w >= N) return;
    const int start = g_off[w];
    const int end   = g_cur[w];
    const int deg   = g_hist[w];

    float4 acc = make_float4(0.f, 0.f, 0.f, 0.f);
    for (int i = start; i < end; i++) {
        uint2 p = g_packed[i];
        float g = __uint_as_float(p.y);
        float4 v = *(const float4*)(h + (size_t)p.x * 128 + lane * 4);
        acc.x += g * v.x; acc.y += g * v.y;
        acc.z += g * v.z; acc.w += g * v.w;
    }
    const float inv = 1.0f / fmaxf((float)deg, 1.0f);
    acc.x *= inv; acc.y *= inv; acc.z *= inv; acc.w *= inv;
    ((float4*)(out + (size_t)w * 128))[lane] = acc;
}

// --------------------------------- launch ----------------------------------

extern "C" void kernel_launch(void* const* d_in, const int* in_sizes, int n_in,
                              void* d_out, int out_size)
{
    const float* x     = (const float*)d_in[0];
    const float* alpha = (const float*)d_in[1];
    const int*   ei    = (const int*)  d_in[2];
    const float* W1 = (const float*)d_in[4];
    const float* b1 = (const float*)d_in[5];
    const float* W2 = (const float*)d_in[6];
    const float* b2 = (const float*)d_in[7];
    const float* W3 = (const float*)d_in[8];
    const float* b3 = (const float*)d_in[9];
    float* out = (float*)d_out;

    const int N = in_sizes[0] / 256;
    const int E = in_sizes[1];

    __half *xhi, *xlo, *h1hi, *h1lo, *h2hi, *h2lo;
    __half *w1h, *w2h, *w3h;
    float *h;
    int *hist;
    cudaGetSymbolAddress((void**)&xhi,  g_xhi);
    cudaGetSymbolAddress((void**)&xlo,  g_xlo);
    cudaGetSymbolAddress((void**)&h1hi, g_h1hi);
    cudaGetSymbolAddress((void**)&h1lo, g_h1lo);
    cudaGetSymbolAddress((void**)&h2hi, g_h2hi);
    cudaGetSymbolAddress((void**)&h2lo, g_h2lo);
    cudaGetSymbolAddress((void**)&w1h,  g_w1h);
    cudaGetSymbolAddress((void**)&w2h,  g_w2h);
    cudaGetSymbolAddress((void**)&w3h,  g_w3h);
    cudaGetSymbolAddress((void**)&h,    g_h);
    cudaGetSymbolAddress((void**)&hist, g_hist);

    const int SMEM_256 = 3 * (2 * 16384 + 256 * 128);   // 196608
    const int SMEM_128 = 3 * (2 * 16384 + 128 * 128);   // 147456
    cudaFuncSetAttribute(gemm_mma<256, 3, true,  true >,
                         cudaFuncAttributeMaxDynamicSharedMemorySize, SMEM_256);
    cudaFuncSetAttribute(gemm_mma<128, 3, false, false>,
                         cudaFuncAttributeMaxDynamicSharedMemorySize, SMEM_128);

    cudaMemsetAsync(hist, 0, (size_t)N * sizeof(int));

    const int mt = (N + 127) / 128;
    const int nb = (N + 255) / 256;
    const int n4x = (N * 256) / 4;
    const int splitTot = n4x + 512 * 256 / 4 + 256 * 512 / 4 + 128 * 256 / 4;

    // kernel #1
    split_all<<<(splitTot + 255) / 256, 256>>>(x, W1, W2, W3, n4x);
    // kernel #2
    hist_kernel<<<(E + 255) / 256, 256>>>(ei, E);
    // kernel #3
    scan_local<<<nb, 256>>>(N);
    // kernel #4  <-- ncu capture slot
    gemm_mma<256, 3, true,  true ><<<dim3(2, mt), 512, SMEM_256>>>(
        xhi, xlo, w1h, b1, h1hi, h1lo, nullptr, N, 512, 256);
    // kernel #5
    scan_top<<<1, 512>>>(nb);
    // kernel #6
    scan_add<<<nb, 256>>>(N);
    // kernel #7
    gemm_mma<256, 3, true,  true ><<<dim3(1, mt), 512, SMEM_256>>>(
        h1hi, h1lo, w2h, b2, h2hi, h2lo, nullptr, N, 256, 512);
    // kernel #8
    reorder_kernel<<<(E + 255) / 256, 256>>>(ei, alpha, E);
    // kernel #9
    gemm_mma<128, 3, false, false><<<dim3(1, mt), 256, SMEM_128>>>(
        h2hi, h2lo, w3h, b3, nullptr, nullptr, h, N, 128, 256);
    // kernel #10
    gather_kernel<<<(N * 32 + 255) / 256, 256>>>(h, out, N);
}

// round 9
// speedup vs baseline: 3.2935x; 1.1250x over previous
#include <cuda_runtime.h>
#include <cuda_fp16.h>
#include <math.h>
#include <stdint.h>

// ---------------------------------------------------------------------------
// FilterGNN round 9: 2-term split GEMM, NT=128 / 256thr / 2 stages
//   -> 96KB smem/CTA -> 2 resident CTAs/SM (was 1) to overlap prologue/
//   epilogue across CTAs and double independent instruction streams.
// Kernel order keeps gemm1 as launch #4 (ncu capture slot).
// ---------------------------------------------------------------------------

#define MAXN 100000
#define MAXE 640000

__device__ __align__(16) __half g_xhi [MAXN * 256];
__device__ __align__(16) __half g_xlo [MAXN * 256];
__device__ __align__(16) __half g_h1hi[MAXN * 512];
__device__ __align__(16) __half g_h1lo[MAXN * 512];
__device__ __align__(16) __half g_h2hi[MAXN * 256];
__device__ __align__(16) __half g_h2lo[MAXN * 256];
__device__ __align__(16) float  g_h   [MAXN * 128];
__device__ __align__(16) __half g_w1h[512 * 256];
__device__ __align__(16) __half g_w2h[256 * 512];
__device__ __align__(16) __half g_w3h[128 * 256];

__device__ int   g_hist[MAXN];
__device__ int   g_off [MAXN];
__device__ int   g_cur [MAXN];
__device__ int   g_part[512];
__device__ uint2 g_packed[MAXE];

// ------------------------------- helpers -----------------------------------

__device__ __forceinline__ uint32_t smem_u32(const void* p) {
    uint32_t a;
    asm("{ .reg .u64 t; cvta.to.shared.u64 t, %1; cvt.u32.u64 %0, t; }"
        : "=r"(a) : "l"(p));
    return a;
}

#define SWZ(off) ((off) ^ (((off) >> 3) & 0x70))

__device__ __forceinline__ void cp16(uint32_t dst, const void* src) {
    asm volatile("cp.async.cg.shared.global [%0], [%1], 16;\n"
                 :: "r"(dst), "l"(src));
}
__device__ __forceinline__ void cp16z(uint32_t dst, const void* src, bool valid) {
    asm volatile("cp.async.cg.shared.global [%0], [%1], 16, %2;\n"
                 :: "r"(dst), "l"(src), "r"(valid ? 16u : 0u));
}
#define CP_COMMIT()  asm volatile("cp.async.commit_group;\n" ::: "memory")
#define CP_WAIT(n)   asm volatile("cp.async.wait_group %0;\n" :: "n"(n) : "memory")

__device__ __forceinline__ void ldm_x4(uint32_t r[4], uint32_t addr) {
    asm volatile("ldmatrix.sync.aligned.m8n8.x4.shared.b16 {%0,%1,%2,%3}, [%4];"
                 : "=r"(r[0]), "=r"(r[1]), "=r"(r[2]), "=r"(r[3]) : "r"(addr));
}

__device__ __forceinline__ void mma16816(float c[4], const uint32_t a[4],
                                         uint32_t b0, uint32_t b1) {
    asm volatile(
        "mma.sync.aligned.m16n8k16.row.col.f32.f16.f16.f32 "
        "{%0,%1,%2,%3}, {%4,%5,%6,%7}, {%8,%9}, {%0,%1,%2,%3};"
        : "+f"(c[0]), "+f"(c[1]), "+f"(c[2]), "+f"(c[3])
        : "r"(a[0]), "r"(a[1]), "r"(a[2]), "r"(a[3]), "r"(b0), "r"(b1));
}

// ------------------------------ fused split --------------------------------

__device__ __forceinline__ void split4(const float* __restrict__ a,
                                       __half* __restrict__ hi,
                                       __half* __restrict__ lo, int i)
{
    float4 v = ((const float4*)a)[i];
    float f[4] = {v.x, v.y, v.z, v.w};
    __half h[4], l[4];
    #pragma unroll
    for (int p = 0; p < 4; p++) {
        h[p] = __float2half_rn(f[p]);
        l[p] = __float2half_rn(f[p] - __half2float(h[p]));
    }
    ((uint2*)hi)[i] = *(uint2*)h;
    ((uint2*)lo)[i] = *(uint2*)l;
}

__device__ __forceinline__ void round4(const float* __restrict__ a,
                                       __half* __restrict__ hi, int i)
{
    float4 v = ((const float4*)a)[i];
    __half h[4] = { __float2half_rn(v.x), __float2half_rn(v.y),
                    __float2half_rn(v.z), __float2half_rn(v.w) };
    ((uint2*)hi)[i] = *(uint2*)h;
}

__global__ void split_all(const float* __restrict__ x,
                          const float* __restrict__ W1,
                          const float* __restrict__ W2,
                          const float* __restrict__ W3, int n4x)
{
    const int nW1 = 512 * 256 / 4, nW2 = 256 * 512 / 4, nW3 = 128 * 256 / 4;
    int i = blockIdx.x * blockDim.x + threadIdx.x;
    if (i < n4x) { split4(x, g_xhi, g_xlo, i); return; }
    i -= n4x;
    if (i < nW1) { round4(W1, g_w1h, i); return; }
    i -= nW1;
    if (i < nW2) { round4(W2, g_w2h, i); return; }
    i -= nW2;
    if (i < nW3) { round4(W3, g_w3h, i); return; }
}

// --------------------------------- GEMM ------------------------------------
// NT=128, 256 threads, 8 warps (wm 0..3, wn 0..1), warp tile 32x64.
// Stage = {Ah 16K | Al 16K | B 16K} = 48KB; 2 stages = 96KB -> 2 CTAs/SM.

__device__ __forceinline__ void fill_chunk128(
    uint32_t sAh, uint32_t sAl, uint32_t sB,
    const __half* __restrict__ Ahi, const __half* __restrict__ Alo,
    const __half* __restrict__ Bh,
    int c, int K, int M, int mBlock, int nBlock, int tid)
{
    const int kk = c << 6;
    #pragma unroll
    for (int i = 0; i < 4; i++) {                 // A hi+lo: 128 rows x 128B
        int s = tid + i * 256;
        int row = s >> 3, byte = (s & 7) << 4;
        int grow = mBlock + row;
        bool v = grow < M;
        size_t base = (size_t)(v ? grow : 0) * K + kk;
        uint32_t soff = SWZ((row << 7) + byte);
        cp16z(sAh + soff, (const char*)(Ahi + base) + byte, v);
        cp16z(sAl + soff, (const char*)(Alo + base) + byte, v);
    }
    #pragma unroll
    for (int i = 0; i < 4; i++) {                 // B: 128 rows x 128B
        int s = tid + i * 256;
        int row = s >> 3, byte = (s & 7) << 4;
        const char* src = (const char*)(Bh + (size_t)(nBlock + row) * K + kk) + byte;
        cp16(sB + SWZ((row << 7) + byte), src);
    }
}

template<bool TANH, bool SPLIT_OUT>
__global__ void __launch_bounds__(256, 2)
gemm_mma(const __half* __restrict__ Ahi, const __half* __restrict__ Alo,
         const __half* __restrict__ Bh,
         const float* __restrict__ bias,
         __half* __restrict__ Ohi, __half* __restrict__ Olo,
         float* __restrict__ Of,
         int M, int Nn, int K)
{
    extern __shared__ char smem[];
    constexpr int A_BYTES = 128 * 128;
    constexpr int STAGE   = 3 * A_BYTES;          // Ah + Al + B
    constexpr int STAGES  = 2;

    const int tid = threadIdx.x;
    const int wid = tid >> 5;
    const int lid = tid & 31;
    const int wm  = wid & 3;
    const int wn  = wid >> 2;                     // 0..1
    const int sb  = wid & 3;                      // k-step stagger
    const int mBlock = blockIdx.y * 128;
    const int nBlock = blockIdx.x * 128;

    const uint32_t sbase = smem_u32(smem);

    float acc[2][8][4];
    #pragma unroll
    for (int i = 0; i < 2; i++)
        #pragma unroll
        for (int j = 0; j < 8; j++)
            #pragma unroll
            for (int q = 0; q < 4; q++) acc[i][j][q] = 0.0f;

    const int NC = K >> 6;

    fill_chunk128(sbase, sbase + A_BYTES, sbase + 2 * A_BYTES,
                  Ahi, Alo, Bh, 0, K, M, mBlock, nBlock, tid);
    CP_COMMIT();

    const int aRow  = lid & 15;
    const int aByte = (lid >> 4) << 4;
    const int bRow  = (((lid >> 4) & 1) << 3) + (lid & 7);
    const int bByte = ((lid >> 3) & 1) << 4;

    const uint32_t aOffBase[2] = {
        (uint32_t)(((wm * 32 +  0 + aRow) << 7)),
        (uint32_t)(((wm * 32 + 16 + aRow) << 7)) };
    const uint32_t aSwz = ((aRow & 7) << 4);
    const uint32_t bOffBase[4] = {
        (uint32_t)(((wn * 64 +  0 + bRow) << 7)),
        (uint32_t)(((wn * 64 + 16 + bRow) << 7)),
        (uint32_t)(((wn * 64 + 32 + bRow) << 7)),
        (uint32_t)(((wn * 64 + 48 + bRow) << 7)) };
    const uint32_t bSwz = ((bRow & 7) << 4);

    for (int c = 0; c < NC; c++) {
        CP_WAIT(0);
        __syncthreads();

        if (c + 1 < NC) {
            uint32_t st = sbase + ((c + 1) & 1) * STAGE;
            fill_chunk128(st, st + A_BYTES, st + 2 * A_BYTES,
                          Ahi, Alo, Bh, c + 1, K, M, mBlock, nBlock, tid);
        }
        CP_COMMIT();

        const uint32_t stAh = sbase + (c & 1) * STAGE;
        const uint32_t stAl = stAh + A_BYTES;
        const uint32_t stB  = stAh + 2 * A_BYTES;

        #pragma unroll
        for (int ss = 0; ss < 4; ss++) {
            const int s = (ss + sb) & 3;
            uint32_t ah[2][4], al[2][4], b[4][4];
            const uint32_t offA = (uint32_t)((32 * s + aByte)) ^ aSwz;
            const uint32_t offB = (uint32_t)((32 * s + bByte)) ^ bSwz;
            ldm_x4(ah[0], stAh + aOffBase[0] + offA);
            ldm_x4(ah[1], stAh + aOffBase[1] + offA);
            ldm_x4(al[0], stAl + aOffBase[0] + offA);
            ldm_x4(al[1], stAl + aOffBase[1] + offA);
            #pragma unroll
            for (int g = 0; g < 4; g++)
                ldm_x4(b[g], stB + bOffBase[g] + offB);

            #pragma unroll
            for (int mi = 0; mi < 2; mi++)
                #pragma unroll
                for (int ni = 0; ni < 8; ni++) {
                    mma16816(acc[mi][ni], ah[mi], b[ni >> 1][(ni & 1) * 2],
                             b[ni >> 1][(ni & 1) * 2 + 1]);
                    mma16816(acc[mi][ni], al[mi], b[ni >> 1][(ni & 1) * 2],
                             b[ni >> 1][(ni & 1) * 2 + 1]);
                }
        }
    }

    const int lid4 = lid >> 2;
    const int lq   = (lid & 3) * 2;
    #pragma unroll
    for (int mi = 0; mi < 2; mi++) {
        #pragma unroll
        for (int rr = 0; rr < 2; rr++) {
            const int row = mBlock + wm * 32 + mi * 16 + rr * 8 + lid4;
            if (row >= M) continue;
            #pragma unroll
            for (int ni = 0; ni < 8; ni++) {
                const int col = nBlock + wn * 64 + ni * 8 + lq;
                float v0 = acc[mi][ni][rr * 2 + 0] + __ldg(&bias[col]);
                float v1 = acc[mi][ni][rr * 2 + 1] + __ldg(&bias[col + 1]);
                if (TANH) { v0 = tanhf(v0); v1 = tanhf(v1); }
                if (SPLIT_OUT) {
                    __half h0 = __float2half_rn(v0), h1 = __float2half_rn(v1);
                    __half l0 = __float2half_rn(v0 - __half2float(h0));
                    __half l1 = __float2half_rn(v1 - __half2float(h1));
                    *(__half2*)(Ohi + (size_t)row * Nn + col) = __halves2half2(h0, h1);
                    *(__half2*)(Olo + (size_t)row * Nn + col) = __halves2half2(l0, l1);
                } else {
                    *(float2*)(Of + (size_t)row * Nn + col) = make_float2(v0, v1);
                }
            }
        }
    }
}

// ------------------------- CSR scatter-mean chain ---------------------------

__global__ void hist_kernel(const int* __restrict__ ei, int E)
{
    int e = blockIdx.x * blockDim.x + threadIdx.x;
    if (e < E) atomicAdd(&g_hist[ei[E + e]], 1);
}

__global__ void scan_local(int n)
{
    __shared__ int wsum[8];
    const int t = threadIdx.x, lane = t & 31, w = t >> 5;
    const int i = blockIdx.x * 256 + t;
    int v = (i < n) ? g_hist[i] : 0;
    int x = v;
    #pragma unroll
    for (int d = 1; d < 32; d <<= 1) {
        int y = __shfl_up_sync(0xFFFFFFFFu, x, d);
        if (lane >= d) x += y;
    }
    if (lane == 31) wsum[w] = x;
    __syncthreads();
    if (t == 0) {
        int run = 0;
        #pragma unroll
        for (int k = 0; k < 8; k++) { int tmp = wsum[k]; wsum[k] = run; run += tmp; }
        g_part[blockIdx.x] = run;
    }
    __syncthreads();
    if (i < n) g_off[i] = x - v + wsum[w];
}

__global__ void scan_top(int nb)
{
    __shared__ int s[512];
    const int t = threadIdx.x;
    s[t] = (t < nb) ? g_part[t] : 0;
    __syncthreads();
    #pragma unroll
    for (int d = 1; d < 512; d <<= 1) {
        int v = (t >= d) ? s[t - d] : 0;
        __syncthreads();
        s[t] += v;
        __syncthreads();
    }
    if (t < nb) g_part[t] = (t == 0) ? 0 : s[t - 1];
}

__global__ void scan_add(int n)
{
    int i = blockIdx.x * 256 + threadIdx.x;
    if (i < n) {
        int o = g_off[i] + g_part[blockIdx.x];
        g_off[i] = o;
        g_cur[i] = o;
    }
}

__global__ void reorder_kernel(const int* __restrict__ ei,
                               const float* __restrict__ alpha, int E)
{
    int e = blockIdx.x * blockDim.x + threadIdx.x;
    if (e >= E) return;
    float gate = 2.0f * fmaxf(alpha[e] - 0.5f, 0.0f);
    if (gate <= 0.0f) return;
    int dst = ei[E + e];
    int pos = atomicAdd(&g_cur[dst], 1);
    g_packed[pos] = make_uint2((unsigned)ei[e], __float_as_uint(gate));
}

__global__ void gather_kernel(const float* __restrict__ h,
                              float* __restrict__ out, int N)
{
    const int w    = (blockIdx.x * blockDim.x + threadIdx.x) >> 5;
    const int lane = threadIdx.x & 31;
    if (w >= N) return;
    const int start = g_off[w];
    const int end   = g_cur[w];
    const int deg   = g_hist[w];

    float4 acc = make_float4(0.f, 0.f, 0.f, 0.f);
    for (int i = start; i < end; i++) {
        uint2 p = g_packed[i];
        float g = __uint_as_float(p.y);
        float4 v = *(const float4*)(h + (size_t)p.x * 128 + lane * 4);
        acc.x += g * v.x; acc.y += g * v.y;
        acc.z += g * v.z; acc.w += g * v.w;
    }
    const float inv = 1.0f / fmaxf((float)deg, 1.0f);
    acc.x *= inv; acc.y *= inv; acc.z *= inv; acc.w *= inv;
    ((float4*)(out + (size_t)w * 128))[lane] = acc;
}

// --------------------------------- launch ----------------------------------

extern "C" void kernel_launch(void* const* d_in, const int* in_sizes, int n_in,
                              void* d_out, int out_size)
{
    const float* x     = (const float*)d_in[0];
    const float* alpha = (const float*)d_in[1];
    const int*   ei    = (const int*)  d_in[2];
    const float* W1 = (const float*)d_in[4];
    const float* b1 = (const float*)d_in[5];
    const float* W2 = (const float*)d_in[6];
    const float* b2 = (const float*)d_in[7];
    const float* W3 = (const float*)d_in[8];
    const float* b3 = (const float*)d_in[9];
    float* out = (float*)d_out;

    const int N = in_sizes[0] / 256;
    const int E = in_sizes[1];

    __half *xhi, *xlo, *h1hi, *h1lo, *h2hi, *h2lo;
    __half *w1h, *w2h, *w3h;
    float *h;
    int *hist;
    cudaGetSymbolAddress((void**)&xhi,  g_xhi);
    cudaGetSymbolAddress((void**)&xlo,  g_xlo);
    cudaGetSymbolAddress((void**)&h1hi, g_h1hi);
    cudaGetSymbolAddress((void**)&h1lo, g_h1lo);
    cudaGetSymbolAddress((void**)&h2hi, g_h2hi);
    cudaGetSymbolAddress((void**)&h2lo, g_h2lo);
    cudaGetSymbolAddress((void**)&w1h,  g_w1h);
    cudaGetSymbolAddress((void**)&w2h,  g_w2h);
    cudaGetSymbolAddress((void**)&w3h,  g_w3h);
    cudaGetSymbolAddress((void**)&h,    g_h);
    cudaGetSymbolAddress((void**)&hist, g_hist);

    const int SMEM_G = 2 * 3 * 16384;     // 98304 bytes, 2 CTAs/SM
    cudaFuncSetAttribute(gemm_mma<true,  true >,
                         cudaFuncAttributeMaxDynamicSharedMemorySize, SMEM_G);
    cudaFuncSetAttribute(gemm_mma<false, false>,
                         cudaFuncAttributeMaxDynamicSharedMemorySize, SMEM_G);

    cudaMemsetAsync(hist, 0, (size_t)N * sizeof(int));

    const int mt = (N + 127) / 128;
    const int nb = (N + 255) / 256;
    const int n4x = (N * 256) / 4;
    const int splitTot = n4x + 512 * 256 / 4 + 256 * 512 / 4 + 128 * 256 / 4;

    // kernel #1
    split_all<<<(splitTot + 255) / 256, 256>>>(x, W1, W2, W3, n4x);
    // kernel #2
    hist_kernel<<<(E + 255) / 256, 256>>>(ei, E);
    // kernel #3
    scan_local<<<nb, 256>>>(N);
    // kernel #4  <-- ncu capture slot
    gemm_mma<true,  true ><<<dim3(4, mt), 256, SMEM_G>>>(
        xhi, xlo, w1h, b1, h1hi, h1lo, nullptr, N, 512, 256);
    // kernel #5
    scan_top<<<1, 512>>>(nb);
    // kernel #6
    scan_add<<<nb, 256>>>(N);
    // kernel #7
    gemm_mma<true,  true ><<<dim3(2, mt), 256, SMEM_G>>>(
        h1hi, h1lo, w2h, b2, h2hi, h2lo, nullptr, N, 256, 512);
    // kernel #8
    reorder_kernel<<<(E + 255) / 256, 256>>>(ei, alpha, E);
    // kernel #9
    gemm_mma<false, false><<<dim3(1, mt), 256, SMEM_G>>>(
        h2hi, h2lo, w3h, b3, nullptr, nullptr, h, N, 128, 256);
    // kernel #10
    gather_kernel<<<(N * 32 + 255) / 256, 256>>>(h, out, N);
}

// round 10
// speedup vs baseline: 3.4199x; 1.0384x over previous
#include <cuda_runtime.h>
#include <cuda_fp16.h>
#include <math.h>
#include <stdint.h>

// ---------------------------------------------------------------------------
// FilterGNN round 10: single-pass fp16 HMMA GEMMs (A and W rounded to fp16,
// fp32 accumulate). Halves tensor FLOPs + A traffic vs R9's 2-term split;
// accuracy budget: measured 4.0e-4 (W-round) -> predicted ~5.7e-4 total.
// NT=128 / 256thr / 3-stage ring / 96KB smem -> 2 CTAs/SM.
// Kernel order keeps gemm1 as launch #4 (ncu capture slot).
// ---------------------------------------------------------------------------

#define MAXN 100000
#define MAXE 640000

__device__ __align__(16) __half g_xh [MAXN * 256];
__device__ __align__(16) __half g_h1h[MAXN * 512];
__device__ __align__(16) __half g_h2h[MAXN * 256];
__device__ __align__(16) float  g_h  [MAXN * 128];
__device__ __align__(16) __half g_w1h[512 * 256];
__device__ __align__(16) __half g_w2h[256 * 512];
__device__ __align__(16) __half g_w3h[128 * 256];

__device__ int   g_hist[MAXN];
__device__ int   g_off [MAXN];
__device__ int   g_cur [MAXN];
__device__ int   g_part[512];
__device__ uint2 g_packed[MAXE];

// ------------------------------- helpers -----------------------------------

__device__ __forceinline__ uint32_t smem_u32(const void* p) {
    uint32_t a;
    asm("{ .reg .u64 t; cvta.to.shared.u64 t, %1; cvt.u32.u64 %0, t; }"
        : "=r"(a) : "l"(p));
    return a;
}

#define SWZ(off) ((off) ^ (((off) >> 3) & 0x70))

__device__ __forceinline__ void cp16(uint32_t dst, const void* src) {
    asm volatile("cp.async.cg.shared.global [%0], [%1], 16;\n"
                 :: "r"(dst), "l"(src));
}
__device__ __forceinline__ void cp16z(uint32_t dst, const void* src, bool valid) {
    asm volatile("cp.async.cg.shared.global [%0], [%1], 16, %2;\n"
                 :: "r"(dst), "l"(src), "r"(valid ? 16u : 0u));
}
#define CP_COMMIT()  asm volatile("cp.async.commit_group;\n" ::: "memory")
#define CP_WAIT(n)   asm volatile("cp.async.wait_group %0;\n" :: "n"(n) : "memory")

__device__ __forceinline__ void ldm_x4(uint32_t r[4], uint32_t addr) {
    asm volatile("ldmatrix.sync.aligned.m8n8.x4.shared.b16 {%0,%1,%2,%3}, [%4];"
                 : "=r"(r[0]), "=r"(r[1]), "=r"(r[2]), "=r"(r[3]) : "r"(addr));
}

__device__ __forceinline__ void mma16816(float c[4], const uint32_t a[4],
                                         uint32_t b0, uint32_t b1) {
    asm volatile(
        "mma.sync.aligned.m16n8k16.row.col.f32.f16.f16.f32 "
        "{%0,%1,%2,%3}, {%4,%5,%6,%7}, {%8,%9}, {%0,%1,%2,%3};"
        : "+f"(c[0]), "+f"(c[1]), "+f"(c[2]), "+f"(c[3])
        : "r"(a[0]), "r"(a[1]), "r"(a[2]), "r"(a[3]), "r"(b0), "r"(b1));
}

// ------------------------------ fused round --------------------------------

__device__ __forceinline__ void round4(const float* __restrict__ a,
                                       __half* __restrict__ hi, int i)
{
    float4 v = ((const float4*)a)[i];
    __half h[4] = { __float2half_rn(v.x), __float2half_rn(v.y),
                    __float2half_rn(v.z), __float2half_rn(v.w) };
    ((uint2*)hi)[i] = *(uint2*)h;
}

__global__ void split_all(const float* __restrict__ x,
                          const float* __restrict__ W1,
                          const float* __restrict__ W2,
                          const float* __restrict__ W3, int n4x)
{
    const int nW1 = 512 * 256 / 4, nW2 = 256 * 512 / 4, nW3 = 128 * 256 / 4;
    int i = blockIdx.x * blockDim.x + threadIdx.x;
    if (i < n4x) { round4(x, g_xh, i); return; }
    i -= n4x;
    if (i < nW1) { round4(W1, g_w1h, i); return; }
    i -= nW1;
    if (i < nW2) { round4(W2, g_w2h, i); return; }
    i -= nW2;
    if (i < nW3) { round4(W3, g_w3h, i); return; }
}

// --------------------------------- GEMM ------------------------------------
// CTA tile 128x128, 256 threads, warp tile 32x64 (wm 0..3, wn 0..1).
// Stage = {A 16K | B 16K} = 32KB; 3 stages = 96KB -> 2 CTAs/SM.

__device__ __forceinline__ void fill_chunk128(
    uint32_t sA, uint32_t sB,
    const __half* __restrict__ Ah, const __half* __restrict__ Bh,
    int c, int K, int M, int mBlock, int nBlock, int tid)
{
    const int kk = c << 6;
    #pragma unroll
    for (int i = 0; i < 4; i++) {                 // A: 128 rows x 128B
        int s = tid + i * 256;
        int row = s >> 3, byte = (s & 7) << 4;
        int grow = mBlock + row;
        bool v = grow < M;
        cp16z(sA + SWZ((row << 7) + byte),
              (const char*)(Ah + (size_t)(v ? grow : 0) * K + kk) + byte, v);
    }
    #pragma unroll
    for (int i = 0; i < 4; i++) {                 // B: 128 rows x 128B
        int s = tid + i * 256;
        int row = s >> 3, byte = (s & 7) << 4;
        cp16(sB + SWZ((row << 7) + byte),
             (const char*)(Bh + (size_t)(nBlock + row) * K + kk) + byte);
    }
}

template<bool TANH, bool HALF_OUT>
__global__ void __launch_bounds__(256, 2)
gemm_mma(const __half* __restrict__ Ah, const __half* __restrict__ Bh,
         const float* __restrict__ bias,
         __half* __restrict__ Oh, float* __restrict__ Of,
         int M, int Nn, int K)
{
    extern __shared__ char smem[];
    constexpr int A_BYTES = 128 * 128;
    constexpr int STAGE   = 2 * A_BYTES;          // A + B
    constexpr int STAGES  = 3;

    const int tid = threadIdx.x;
    const int wid = tid >> 5;
    const int lid = tid & 31;
    const int wm  = wid & 3;
    const int wn  = wid >> 2;                     // 0..1
    const int sb  = wid & 3;                      // k-step stagger
    const int mBlock = blockIdx.y * 128;
    const int nBlock = blockIdx.x * 128;

    const uint32_t sbase = smem_u32(smem);

    float acc[2][8][4];
    #pragma unroll
    for (int i = 0; i < 2; i++)
        #pragma unroll
        for (int j = 0; j < 8; j++)
            #pragma unroll
            for (int q = 0; q < 4; q++) acc[i][j][q] = 0.0f;

    const int NC = K >> 6;

    // prologue: chunks 0,1
    fill_chunk128(sbase, sbase + A_BYTES, Ah, Bh, 0, K, M, mBlock, nBlock, tid);
    CP_COMMIT();
    if (1 < NC) {
        uint32_t st = sbase + STAGE;
        fill_chunk128(st, st + A_BYTES, Ah, Bh, 1, K, M, mBlock, nBlock, tid);
    }
    CP_COMMIT();

    const int aRow  = lid & 15;
    const int aByte = (lid >> 4) << 4;
    const int bRow  = (((lid >> 4) & 1) << 3) + (lid & 7);
    const int bByte = ((lid >> 3) & 1) << 4;

    const uint32_t aOffBase[2] = {
        (uint32_t)(((wm * 32 +  0 + aRow) << 7)),
        (uint32_t)(((wm * 32 + 16 + aRow) << 7)) };
    const uint32_t aSwz = ((aRow & 7) << 4);
    const uint32_t bOffBase[4] = {
        (uint32_t)(((wn * 64 +  0 + bRow) << 7)),
        (uint32_t)(((wn * 64 + 16 + bRow) << 7)),
        (uint32_t)(((wn * 64 + 32 + bRow) << 7)),
        (uint32_t)(((wn * 64 + 48 + bRow) << 7)) };
    const uint32_t bSwz = ((bRow & 7) << 4);

    for (int c = 0; c < NC; c++) {
        CP_WAIT(1);                    // chunk c resident
        __syncthreads();               // all warps done with stage (c-1)%3

        if (c + 2 < NC) {
            uint32_t st = sbase + ((c + 2) % STAGES) * STAGE;
            fill_chunk128(st, st + A_BYTES, Ah, Bh, c + 2, K, M,
                          mBlock, nBlock, tid);
        }
        CP_COMMIT();

        const uint32_t stA = sbase + (c % STAGES) * STAGE;
        const uint32_t stB = stA + A_BYTES;

        #pragma unroll
        for (int ss = 0; ss < 4; ss++) {
            const int s = (ss + sb) & 3;
            uint32_t a[2][4], b[4][4];
            const uint32_t offA = (uint32_t)((32 * s + aByte)) ^ aSwz;
            const uint32_t offB = (uint32_t)((32 * s + bByte)) ^ bSwz;
            ldm_x4(a[0], stA + aOffBase[0] + offA);
            ldm_x4(a[1], stA + aOffBase[1] + offA);
            #pragma unroll
            for (int g = 0; g < 4; g++)
                ldm_x4(b[g], stB + bOffBase[g] + offB);

            #pragma unroll
            for (int mi = 0; mi < 2; mi++)
                #pragma unroll
                for (int ni = 0; ni < 8; ni++)
                    mma16816(acc[mi][ni], a[mi], b[ni >> 1][(ni & 1) * 2],
                             b[ni >> 1][(ni & 1) * 2 + 1]);
        }
    }

    const int lid4 = lid >> 2;
    const int lq   = (lid & 3) * 2;
    #pragma unroll
    for (int mi = 0; mi < 2; mi++) {
        #pragma unroll
        for (int rr = 0; rr < 2; rr++) {
            const int row = mBlock + wm * 32 + mi * 16 + rr * 8 + lid4;
            if (row >= M) continue;
            #pragma unroll
            for (int ni = 0; ni < 8; ni++) {
                const int col = nBlock + wn * 64 + ni * 8 + lq;
                float v0 = acc[mi][ni][rr * 2 + 0] + __ldg(&bias[col]);
                float v1 = acc[mi][ni][rr * 2 + 1] + __ldg(&bias[col + 1]);
                if (TANH) { v0 = tanhf(v0); v1 = tanhf(v1); }
                if (HALF_OUT) {
                    *(__half2*)(Oh + (size_t)row * Nn + col) =
                        __halves2half2(__float2half_rn(v0), __float2half_rn(v1));
                } else {
                    *(float2*)(Of + (size_t)row * Nn + col) = make_float2(v0, v1);
                }
            }
        }
    }
}

// ------------------------- CSR scatter-mean chain ---------------------------

__global__ void hist_kernel(const int* __restrict__ ei, int E)
{
    int e = blockIdx.x * blockDim.x + threadIdx.x;
    if (e < E) atomicAdd(&g_hist[ei[E + e]], 1);
}

__global__ void scan_local(int n)
{
    __shared__ int wsum[8];
    const int t = threadIdx.x, lane = t & 31, w = t >> 5;
    const int i = blockIdx.x * 256 + t;
    int v = (i < n) ? g_hist[i] : 0;
    int x = v;
    #pragma unroll
    for (int d = 1; d < 32; d <<= 1) {
        int y = __shfl_up_sync(0xFFFFFFFFu, x, d);
        if (lane >= d) x += y;
    }
    if (lane == 31) wsum[w] = x;
    __syncthreads();
    if (t == 0) {
        int run = 0;
        #pragma unroll
        for (int k = 0; k < 8; k++) { int tmp = wsum[k]; wsum[k] = run; run += tmp; }
        g_part[blockIdx.x] = run;
    }
    __syncthreads();
    if (i < n) g_off[i] = x - v + wsum[w];
}

__global__ void scan_top(int nb)
{
    __shared__ int s[512];
    const int t = threadIdx.x;
    s[t] = (t < nb) ? g_part[t] : 0;
    __syncthreads();
    #pragma unroll
    for (int d = 1; d < 512; d <<= 1) {
        int v = (t >= d) ? s[t - d] : 0;
        __syncthreads();
        s[t] += v;
        __syncthreads();
    }
    if (t < nb) g_part[t] = (t == 0) ? 0 : s[t - 1];
}

__global__ void scan_add(int n)
{
    int i = blockIdx.x * 256 + threadIdx.x;
    if (i < n) {
        int o = g_off[i] + g_part[blockIdx.x];
        g_off[i] = o;
        g_cur[i] = o;
    }
}

__global__ void reorder_kernel(const int* __restrict__ ei,
                               const float* __restrict__ alpha, int E)
{
    int e = blockIdx.x * blockDim.x + threadIdx.x;
    if (e >= E) return;
    float gate = 2.0f * fmaxf(alpha[e] - 0.5f, 0.0f);
    if (gate <= 0.0f) return;
    int dst = ei[E + e];
    int pos = atomicAdd(&g_cur[dst], 1);
    g_packed[pos] = make_uint2((unsigned)ei[e], __float_as_uint(gate));
}

__global__ void gather_kernel(const float* __restrict__ h,
                              float* __restrict__ out, int N)
{
    const int w    = (blockIdx.x * blockDim.x + threadIdx.x) >> 5;
    const int lane = threadIdx.x & 31;
    if (w >= N) return;
    const int start = g_off[w];
    const int end   = g_cur[w];
    const int deg   = g_hist[w];

    float4 acc = make_float4(0.f, 0.f, 0.f, 0.f);
    for (int i = start; i < end; i++) {
        uint2 p = g_packed[i];
        float g = __uint_as_float(p.y);
        float4 v = *(const float4*)(h + (size_t)p.x * 128 + lane * 4);
        acc.x += g * v.x; acc.y += g * v.y;
        acc.z += g * v.z; acc.w += g * v.w;
    }
    const float inv = 1.0f / fmaxf((float)deg, 1.0f);
    acc.x *= inv; acc.y *= inv; acc.z *= inv; acc.w *= inv;
    ((float4*)(out + (size_t)w * 128))[lane] = acc;
}

// --------------------------------- launch ----------------------------------

extern "C" void kernel_launch(void* const* d_in, const int* in_sizes, int n_in,
                              void* d_out, int out_size)
{
    const float* x     = (const float*)d_in[0];
    const float* alpha = (const float*)d_in[1];
    const int*   ei    = (const int*)  d_in[2];
    const float* W1 = (const float*)d_in[4];
    const float* b1 = (const float*)d_in[5];
    const float* W2 = (const float*)d_in[6];
    const float* b2 = (const float*)d_in[7];
    const float* W3 = (const float*)d_in[8];
    const float* b3 = (const float*)d_in[9];
    float* out = (float*)d_out;

    const int N = in_sizes[0] / 256;
    const int E = in_sizes[1];

    __half *xh, *h1h, *h2h, *w1h, *w2h, *w3h;
    float *h;
    int *hist;
    cudaGetSymbolAddress((void**)&xh,   g_xh);
    cudaGetSymbolAddress((void**)&h1h,  g_h1h);
    cudaGetSymbolAddress((void**)&h2h,  g_h2h);
    cudaGetSymbolAddress((void**)&w1h,  g_w1h);
    cudaGetSymbolAddress((void**)&w2h,  g_w2h);
    cudaGetSymbolAddress((void**)&w3h,  g_w3h);
    cudaGetSymbolAddress((void**)&h,    g_h);
    cudaGetSymbolAddress((void**)&hist, g_hist);

    const int SMEM_G = 3 * 2 * 16384;     // 98304 bytes; 2 CTAs/SM
    cudaFuncSetAttribute(gemm_mma<true,  true >,
                         cudaFuncAttributeMaxDynamicSharedMemorySize, SMEM_G);
    cudaFuncSetAttribute(gemm_mma<false, false>,
                         cudaFuncAttributeMaxDynamicSharedMemorySize, SMEM_G);

    cudaMemsetAsync(hist, 0, (size_t)N * sizeof(int));

    const int mt = (N + 127) / 128;
    const int nb = (N + 255) / 256;
    const int n4x = (N * 256) / 4;
    const int splitTot = n4x + 512 * 256 / 4 + 256 * 512 / 4 + 128 * 256 / 4;

    // kernel #1
    split_all<<<(splitTot + 255) / 256, 256>>>(x, W1, W2, W3, n4x);
    // kernel #2
    hist_kernel<<<(E + 255) / 256, 256>>>(ei, E);
    // kernel #3
    scan_local<<<nb, 256>>>(N);
    // kernel #4  <-- ncu capture slot
    gemm_mma<true,  true ><<<dim3(4, mt), 256, SMEM_G>>>(
        xh, w1h, b1, h1h, nullptr, N, 512, 256);
    // kernel #5
    scan_top<<<1, 512>>>(nb);
    // kernel #6
    scan_add<<<nb, 256>>>(N);
    // kernel #7
    gemm_mma<true,  true ><<<dim3(2, mt), 256, SMEM_G>>>(
        h1h, w2h, b2, h2h, nullptr, N, 256, 512);
    // kernel #8
    reorder_kernel<<<(E + 255) / 256, 256>>>(ei, alpha, E);
    // kernel #9
    gemm_mma<false, false><<<dim3(1, mt), 256, SMEM_G>>>(
        h2h, w3h, b3, nullptr, h, N, 128, 256);
    // kernel #10
    gather_kernel<<<(N * 32 + 255) / 256, 256>>>(h, out, N);
}

// round 11
// speedup vs baseline: 3.6339x; 1.0626x over previous
#include <cuda_runtime.h>
#include <cuda_fp16.h>
#include <math.h>
#include <stdint.h>

// ---------------------------------------------------------------------------
// FilterGNN round 11: single-pass fp16 HMMA GEMMs + MUFU-based fast tanh
// epilogue (ex2.approx + rcp.approx, ~1e-6 err) + register bias preload +
// fp16 h for the gather stage.
// NT=128 / 256thr / 3-stage ring / 96KB smem -> 2 CTAs/SM.
// Kernel order keeps gemm1 as launch #4 (ncu capture slot).
// ---------------------------------------------------------------------------

#define MAXN 100000
#define MAXE 640000

__device__ __align__(16) __half g_xh [MAXN * 256];
__device__ __align__(16) __half g_h1h[MAXN * 512];
__device__ __align__(16) __half g_h2h[MAXN * 256];
__device__ __align__(16) __half g_hh [MAXN * 128];
__device__ __align__(16) __half g_w1h[512 * 256];
__device__ __align__(16) __half g_w2h[256 * 512];
__device__ __align__(16) __half g_w3h[128 * 256];

__device__ int   g_hist[MAXN];
__device__ int   g_off [MAXN];
__device__ int   g_cur [MAXN];
__device__ int   g_part[512];
__device__ uint2 g_packed[MAXE];

// ------------------------------- helpers -----------------------------------

__device__ __forceinline__ uint32_t smem_u32(const void* p) {
    uint32_t a;
    asm("{ .reg .u64 t; cvta.to.shared.u64 t, %1; cvt.u32.u64 %0, t; }"
        : "=r"(a) : "l"(p));
    return a;
}

#define SWZ(off) ((off) ^ (((off) >> 3) & 0x70))

__device__ __forceinline__ void cp16(uint32_t dst, const void* src) {
    asm volatile("cp.async.cg.shared.global [%0], [%1], 16;\n"
                 :: "r"(dst), "l"(src));
}
__device__ __forceinline__ void cp16z(uint32_t dst, const void* src, bool valid) {
    asm volatile("cp.async.cg.shared.global [%0], [%1], 16, %2;\n"
                 :: "r"(dst), "l"(src), "r"(valid ? 16u : 0u));
}
#define CP_COMMIT()  asm volatile("cp.async.commit_group;\n" ::: "memory")
#define CP_WAIT(n)   asm volatile("cp.async.wait_group %0;\n" :: "n"(n) : "memory")

__device__ __forceinline__ void ldm_x4(uint32_t r[4], uint32_t addr) {
    asm volatile("ldmatrix.sync.aligned.m8n8.x4.shared.b16 {%0,%1,%2,%3}, [%4];"
                 : "=r"(r[0]), "=r"(r[1]), "=r"(r[2]), "=r"(r[3]) : "r"(addr));
}

__device__ __forceinline__ void mma16816(float c[4], const uint32_t a[4],
                                         uint32_t b0, uint32_t b1) {
    asm volatile(
        "mma.sync.aligned.m16n8k16.row.col.f32.f16.f16.f32 "
        "{%0,%1,%2,%3}, {%4,%5,%6,%7}, {%8,%9}, {%0,%1,%2,%3};"
        : "+f"(c[0]), "+f"(c[1]), "+f"(c[2]), "+f"(c[3])
        : "r"(a[0]), "r"(a[1]), "r"(a[2]), "r"(a[3]), "r"(b0), "r"(b1));
}

// tanh(x) = 1 - 2 / (exp2(x * 2/ln2) + 1); MUFU ex2/rcp are ~2^-22 accurate.
__device__ __forceinline__ float fast_tanh(float x) {
    float e, r;
    asm("ex2.approx.f32 %0, %1;" : "=f"(e) : "f"(x * 2.885390081777927f));
    asm("rcp.approx.f32 %0, %1;" : "=f"(r) : "f"(e + 1.0f));
    return fmaf(-2.0f, r, 1.0f);
}

// ------------------------------ fused round --------------------------------

__device__ __forceinline__ void round4(const float* __restrict__ a,
                                       __half* __restrict__ hi, int i)
{
    float4 v = ((const float4*)a)[i];
    __half h[4] = { __float2half_rn(v.x), __float2half_rn(v.y),
                    __float2half_rn(v.z), __float2half_rn(v.w) };
    ((uint2*)hi)[i] = *(uint2*)h;
}

__global__ void split_all(const float* __restrict__ x,
                          const float* __restrict__ W1,
                          const float* __restrict__ W2,
                          const float* __restrict__ W3, int n4x)
{
    const int nW1 = 512 * 256 / 4, nW2 = 256 * 512 / 4, nW3 = 128 * 256 / 4;
    int i = blockIdx.x * blockDim.x + threadIdx.x;
    if (i < n4x) { round4(x, g_xh, i); return; }
    i -= n4x;
    if (i < nW1) { round4(W1, g_w1h, i); return; }
    i -= nW1;
    if (i < nW2) { round4(W2, g_w2h, i); return; }
    i -= nW2;
    if (i < nW3) { round4(W3, g_w3h, i); return; }
}

// --------------------------------- GEMM ------------------------------------
// CTA tile 128x128, 256 threads, warp tile 32x64 (wm 0..3, wn 0..1).
// Stage = {A 16K | B 16K} = 32KB; 3 stages = 96KB -> 2 CTAs/SM.

__device__ __forceinline__ void fill_chunk128(
    uint32_t sA, uint32_t sB,
    const __half* __restrict__ Ah, const __half* __restrict__ Bh,
    int c, int K, int M, int mBlock, int nBlock, int tid)
{
    const int kk = c << 6;
    #pragma unroll
    for (int i = 0; i < 4; i++) {                 // A: 128 rows x 128B
        int s = tid + i * 256;
        int row = s >> 3, byte = (s & 7) << 4;
        int grow = mBlock + row;
        bool v = grow < M;
        cp16z(sA + SWZ((row << 7) + byte),
              (const char*)(Ah + (size_t)(v ? grow : 0) * K + kk) + byte, v);
    }
    #pragma unroll
    for (int i = 0; i < 4; i++) {                 // B: 128 rows x 128B
        int s = tid + i * 256;
        int row = s >> 3, byte = (s & 7) << 4;
        cp16(sB + SWZ((row << 7) + byte),
             (const char*)(Bh + (size_t)(nBlock + row) * K + kk) + byte);
    }
}

template<bool TANH, bool HALF_OUT>
__global__ void __launch_bounds__(256, 2)
gemm_mma(const __half* __restrict__ Ah, const __half* __restrict__ Bh,
         const float* __restrict__ bias,
         __half* __restrict__ Oh, float* __restrict__ Of,
         int M, int Nn, int K)
{
    extern __shared__ char smem[];
    constexpr int A_BYTES = 128 * 128;
    constexpr int STAGE   = 2 * A_BYTES;          // A + B
    constexpr int STAGES  = 3;

    const int tid = threadIdx.x;
    const int wid = tid >> 5;
    const int lid = tid & 31;
    const int wm  = wid & 3;
    const int wn  = wid >> 2;                     // 0..1
    const int sb  = wid & 3;                      // k-step stagger
    const int mBlock = blockIdx.y * 128;
    const int nBlock = blockIdx.x * 128;

    const uint32_t sbase = smem_u32(smem);

    float acc[2][8][4];
    #pragma unroll
    for (int i = 0; i < 2; i++)
        #pragma unroll
        for (int j = 0; j < 8; j++)
            #pragma unroll
            for (int q = 0; q < 4; q++) acc[i][j][q] = 0.0f;

    const int NC = K >> 6;

    // prologue: chunks 0,1
    fill_chunk128(sbase, sbase + A_BYTES, Ah, Bh, 0, K, M, mBlock, nBlock, tid);
    CP_COMMIT();
    if (1 < NC) {
        uint32_t st = sbase + STAGE;
        fill_chunk128(st, st + A_BYTES, Ah, Bh, 1, K, M, mBlock, nBlock, tid);
    }
    CP_COMMIT();

    const int aRow  = lid & 15;
    const int aByte = (lid >> 4) << 4;
    const int bRow  = (((lid >> 4) & 1) << 3) + (lid & 7);
    const int bByte = ((lid >> 3) & 1) << 4;

    const uint32_t aOffBase[2] = {
        (uint32_t)(((wm * 32 +  0 + aRow) << 7)),
        (uint32_t)(((wm * 32 + 16 + aRow) << 7)) };
    const uint32_t aSwz = ((aRow & 7) << 4);
    const uint32_t bOffBase[4] = {
        (uint32_t)(((wn * 64 +  0 + bRow) << 7)),
        (uint32_t)(((wn * 64 + 16 + bRow) << 7)),
        (uint32_t)(((wn * 64 + 32 + bRow) << 7)),
        (uint32_t)(((wn * 64 + 48 + bRow) << 7)) };
    const uint32_t bSwz = ((bRow & 7) << 4);

    for (int c = 0; c < NC; c++) {
        CP_WAIT(1);                    // chunk c resident
        __syncthreads();               // all warps done with stage (c-1)%3

        if (c + 2 < NC) {
            uint32_t st = sbase + ((c + 2) % STAGES) * STAGE;
            fill_chunk128(st, st + A_BYTES, Ah, Bh, c + 2, K, M,
                          mBlock, nBlock, tid);
        }
        CP_COMMIT();

        const uint32_t stA = sbase + (c % STAGES) * STAGE;
        const uint32_t stB = stA + A_BYTES;

        #pragma unroll
        for (int ss = 0; ss < 4; ss++) {
            const int s = (ss + sb) & 3;
            uint32_t a[2][4], b[4][4];
            const uint32_t offA = (uint32_t)((32 * s + aByte)) ^ aSwz;
            const uint32_t offB = (uint32_t)((32 * s + bByte)) ^ bSwz;
            ldm_x4(a[0], stA + aOffBase[0] + offA);
            ldm_x4(a[1], stA + aOffBase[1] + offA);
            #pragma unroll
            for (int g = 0; g < 4; g++)
                ldm_x4(b[g], stB + bOffBase[g] + offB);

            #pragma unroll
            for (int mi = 0; mi < 2; mi++)
                #pragma unroll
                for (int ni = 0; ni < 8; ni++)
                    mma16816(acc[mi][ni], a[mi], b[ni >> 1][(ni & 1) * 2],
                             b[ni >> 1][(ni & 1) * 2 + 1]);
        }
    }

    // ------------------------------ epilogue --------------------------------
    const int lid4 = lid >> 2;
    const int lq   = (lid & 3) * 2;

    // preload this thread's 16 bias values once
    float bc[8][2];
    #pragma unroll
    for (int ni = 0; ni < 8; ni++) {
        float2 bv = *(const float2*)(bias + nBlock + wn * 64 + ni * 8 + lq);
        bc[ni][0] = bv.x; bc[ni][1] = bv.y;
    }

    #pragma unroll
    for (int mi = 0; mi < 2; mi++) {
        #pragma unroll
        for (int rr = 0; rr < 2; rr++) {
            const int row = mBlock + wm * 32 + mi * 16 + rr * 8 + lid4;
            if (row >= M) continue;
            #pragma unroll
            for (int ni = 0; ni < 8; ni++) {
                const int col = nBlock + wn * 64 + ni * 8 + lq;
                float v0 = acc[mi][ni][rr * 2 + 0] + bc[ni][0];
                float v1 = acc[mi][ni][rr * 2 + 1] + bc[ni][1];
                if (TANH) { v0 = fast_tanh(v0); v1 = fast_tanh(v1); }
                if (HALF_OUT) {
                    *(__half2*)(Oh + (size_t)row * Nn + col) =
                        __halves2half2(__float2half_rn(v0), __float2half_rn(v1));
                } else {
                    *(float2*)(Of + (size_t)row * Nn + col) = make_float2(v0, v1);
                }
            }
        }
    }
}

// ------------------------- CSR scatter-mean chain ---------------------------

__global__ void hist_kernel(const int* __restrict__ ei, int E)
{
    int e = blockIdx.x * blockDim.x + threadIdx.x;
    if (e < E) atomicAdd(&g_hist[ei[E + e]], 1);
}

__global__ void scan_local(int n)
{
    __shared__ int wsum[8];
    const int t = threadIdx.x, lane = t & 31, w = t >> 5;
    const int i = blockIdx.x * 256 + t;
    int v = (i < n) ? g_hist[i] : 0;
    int x = v;
    #pragma unroll
    for (int d = 1; d < 32; d <<= 1) {
        int y = __shfl_up_sync(0xFFFFFFFFu, x, d);
        if (lane >= d) x += y;
    }
    if (lane == 31) wsum[w] = x;
    __syncthreads();
    if (t == 0) {
        int run = 0;
        #pragma unroll
        for (int k = 0; k < 8; k++) { int tmp = wsum[k]; wsum[k] = run; run += tmp; }
        g_part[blockIdx.x] = run;
    }
    __syncthreads();
    if (i < n) g_off[i] = x - v + wsum[w];
}

__global__ void scan_top(int nb)
{
    __shared__ int s[512];
    const int t = threadIdx.x;
    s[t] = (t < nb) ? g_part[t] : 0;
    __syncthreads();
    #pragma unroll
    for (int d = 1; d < 512; d <<= 1) {
        int v = (t >= d) ? s[t - d] : 0;
        __syncthreads();
        s[t] += v;
        __syncthreads();
    }
    if (t < nb) g_part[t] = (t == 0) ? 0 : s[t - 1];
}

__global__ void scan_add(int n)
{
    int i = blockIdx.x * 256 + threadIdx.x;
    if (i < n) {
        int o = g_off[i] + g_part[blockIdx.x];
        g_off[i] = o;
        g_cur[i] = o;
    }
}

__global__ void reorder_kernel(const int* __restrict__ ei,
                               const float* __restrict__ alpha, int E)
{
    int e = blockIdx.x * blockDim.x + threadIdx.x;
    if (e >= E) return;
    float gate = 2.0f * fmaxf(alpha[e] - 0.5f, 0.0f);
    if (gate <= 0.0f) return;
    int dst = ei[E + e];
    int pos = atomicAdd(&g_cur[dst], 1);
    g_packed[pos] = make_uint2((unsigned)ei[e], __float_as_uint(gate));
}

// warp per dst: sum gated fp16 messages in fp32, divide by degree, write
__global__ void gather_kernel(const __half* __restrict__ hh,
                              float* __restrict__ out, int N)
{
    const int w    = (blockIdx.x * blockDim.x + threadIdx.x) >> 5;
    const int lane = threadIdx.x & 31;
    if (w >= N) return;
    const int start = g_off[w];
    const int end   = g_cur[w];
    const int deg   = g_hist[w];

    float4 acc = make_float4(0.f, 0.f, 0.f, 0.f);
    for (int i = start; i < end; i++) {
        uint2 p = g_packed[i];
        float g = __uint_as_float(p.y);
        uint2 hv = *(const uint2*)(hh + (size_t)p.x * 128 + lane * 4);
        float2 v01 = __half22float2(*(__half2*)&hv.x);
        float2 v23 = __half22float2(*(__half2*)&hv.y);
        acc.x += g * v01.x; acc.y += g * v01.y;
        acc.z += g * v23.x; acc.w += g * v23.y;
    }
    const float inv = 1.0f / fmaxf((float)deg, 1.0f);
    acc.x *= inv; acc.y *= inv; acc.z *= inv; acc.w *= inv;
    ((float4*)(out + (size_t)w * 128))[lane] = acc;
}

// --------------------------------- launch ----------------------------------

extern "C" void kernel_launch(void* const* d_in, const int* in_sizes, int n_in,
                              void* d_out, int out_size)
{
    const float* x     = (const float*)d_in[0];
    const float* alpha = (const float*)d_in[1];
    const int*   ei    = (const int*)  d_in[2];
    const float* W1 = (const float*)d_in[4];
    const float* b1 = (const float*)d_in[5];
    const float* W2 = (const float*)d_in[6];
    const float* b2 = (const float*)d_in[7];
    const float* W3 = (const float*)d_in[8];
    const float* b3 = (const float*)d_in[9];
    float* out = (float*)d_out;

    const int N = in_sizes[0] / 256;
    const int E = in_sizes[1];

    __half *xh, *h1h, *h2h, *hh, *w1h, *w2h, *w3h;
    int *hist;
    cudaGetSymbolAddress((void**)&xh,   g_xh);
    cudaGetSymbolAddress((void**)&h1h,  g_h1h);
    cudaGetSymbolAddress((void**)&h2h,  g_h2h);
    cudaGetSymbolAddress((void**)&hh,   g_hh);
    cudaGetSymbolAddress((void**)&w1h,  g_w1h);
    cudaGetSymbolAddress((void**)&w2h,  g_w2h);
    cudaGetSymbolAddress((void**)&w3h,  g_w3h);
    cudaGetSymbolAddress((void**)&hist, g_hist);

    const int SMEM_G = 3 * 2 * 16384;     // 98304 bytes; 2 CTAs/SM
    cudaFuncSetAttribute(gemm_mma<true,  true>,
                         cudaFuncAttributeMaxDynamicSharedMemorySize, SMEM_G);
    cudaFuncSetAttribute(gemm_mma<false, true>,
                         cudaFuncAttributeMaxDynamicSharedMemorySize, SMEM_G);

    cudaMemsetAsync(hist, 0, (size_t)N * sizeof(int));

    const int mt = (N + 127) / 128;
    const int nb = (N + 255) / 256;
    const int n4x = (N * 256) / 4;
    const int splitTot = n4x + 512 * 256 / 4 + 256 * 512 / 4 + 128 * 256 / 4;

    // kernel #1
    split_all<<<(splitTot + 255) / 256, 256>>>(x, W1, W2, W3, n4x);
    // kernel #2
    hist_kernel<<<(E + 255) / 256, 256>>>(ei, E);
    // kernel #3
    scan_local<<<nb, 256>>>(N);
    // kernel #4  <-- ncu capture slot
    gemm_mma<true,  true><<<dim3(4, mt), 256, SMEM_G>>>(
        xh, w1h, b1, h1h, nullptr, N, 512, 256);
    // kernel #5
    scan_top<<<1, 512>>>(nb);
    // kernel #6
    scan_add<<<nb, 256>>>(N);
    // kernel #7
    gemm_mma<true,  true><<<dim3(2, mt), 256, SMEM_G>>>(
        h1h, w2h, b2, h2h, nullptr, N, 256, 512);
    // kernel #8
    reorder_kernel<<<(E + 255) / 256, 256>>>(ei, alpha, E);
    // kernel #9
    gemm_mma<false, true><<<dim3(1, mt), 256, SMEM_G>>>(
        h2h, w3h, b3, hh, nullptr, N, 128, 256);
    // kernel #10
    gather_kernel<<<(N * 32 + 255) / 256, 256>>>(hh, out, N);
}

// round 12
// speedup vs baseline: 5.3717x; 1.4782x over previous
#include <cuda_runtime.h>
#include <cuda_fp16.h>
#include <math.h>
#include <stdint.h>

// ---------------------------------------------------------------------------
// FilterGNN round 12: single-pass fp16 HMMA GEMMs + hoisted fill addressing
// (loop-invariant swizzled smem offsets + global row offsets precomputed once;
// per-chunk fill is just add + cp.async). Launch order now profiles gemm2.
//   1 split  2 GEMM1  3 hist  4 GEMM2(capture)  5-7 scans  8 reorder
//   9 GEMM3  10 gather
// ---------------------------------------------------------------------------

#define MAXN 100000
#define MAXE 640000

__device__ __align__(16) __half g_xh [MAXN * 256];
__device__ __align__(16) __half g_h1h[MAXN * 512];
__device__ __align__(16) __half g_h2h[MAXN * 256];
__device__ __align__(16) __half g_hh [MAXN * 128];
__device__ __align__(16) __half g_w1h[512 * 256];
__device__ __align__(16) __half g_w2h[256 * 512];
__device__ __align__(16) __half g_w3h[128 * 256];

__device__ int   g_hist[MAXN];
__device__ int   g_off [MAXN];
__device__ int   g_cur [MAXN];
__device__ int   g_part[512];
__device__ uint2 g_packed[MAXE];

// ------------------------------- helpers -----------------------------------

__device__ __forceinline__ uint32_t smem_u32(const void* p) {
    uint32_t a;
    asm("{ .reg .u64 t; cvta.to.shared.u64 t, %1; cvt.u32.u64 %0, t; }"
        : "=r"(a) : "l"(p));
    return a;
}

#define SWZ(off) ((off) ^ (((off) >> 3) & 0x70))

__device__ __forceinline__ void cp16(uint32_t dst, const void* src) {
    asm volatile("cp.async.cg.shared.global [%0], [%1], 16;\n"
                 :: "r"(dst), "l"(src));
}
__device__ __forceinline__ void cp16z(uint32_t dst, const void* src, bool valid) {
    asm volatile("cp.async.cg.shared.global [%0], [%1], 16, %2;\n"
                 :: "r"(dst), "l"(src), "r"(valid ? 16u : 0u));
}
#define CP_COMMIT()  asm volatile("cp.async.commit_group;\n" ::: "memory")
#define CP_WAIT(n)   asm volatile("cp.async.wait_group %0;\n" :: "n"(n) : "memory")

__device__ __forceinline__ void ldm_x4(uint32_t r[4], uint32_t addr) {
    asm volatile("ldmatrix.sync.aligned.m8n8.x4.shared.b16 {%0,%1,%2,%3}, [%4];"
                 : "=r"(r[0]), "=r"(r[1]), "=r"(r[2]), "=r"(r[3]) : "r"(addr));
}

__device__ __forceinline__ void mma16816(float c[4], const uint32_t a[4],
                                         uint32_t b0, uint32_t b1) {
    asm volatile(
        "mma.sync.aligned.m16n8k16.row.col.f32.f16.f16.f32 "
        "{%0,%1,%2,%3}, {%4,%5,%6,%7}, {%8,%9}, {%0,%1,%2,%3};"
        : "+f"(c[0]), "+f"(c[1]), "+f"(c[2]), "+f"(c[3])
        : "r"(a[0]), "r"(a[1]), "r"(a[2]), "r"(a[3]), "r"(b0), "r"(b1));
}

// tanh(x) = 1 - 2 / (exp2(x * 2/ln2) + 1); MUFU ex2/rcp are ~2^-22 accurate.
__device__ __forceinline__ float fast_tanh(float x) {
    float e, r;
    asm("ex2.approx.f32 %0, %1;" : "=f"(e) : "f"(x * 2.885390081777927f));
    asm("rcp.approx.f32 %0, %1;" : "=f"(r) : "f"(e + 1.0f));
    return fmaf(-2.0f, r, 1.0f);
}

// ------------------------------ fused round --------------------------------

__device__ __forceinline__ void round4(const float* __restrict__ a,
                                       __half* __restrict__ hi, int i)
{
    float4 v = ((const float4*)a)[i];
    __half h[4] = { __float2half_rn(v.x), __float2half_rn(v.y),
                    __float2half_rn(v.z), __float2half_rn(v.w) };
    ((uint2*)hi)[i] = *(uint2*)h;
}

__global__ void split_all(const float* __restrict__ x,
                          const float* __restrict__ W1,
                          const float* __restrict__ W2,
                          const float* __restrict__ W3, int n4x)
{
    const int nW1 = 512 * 256 / 4, nW2 = 256 * 512 / 4, nW3 = 128 * 256 / 4;
    int i = blockIdx.x * blockDim.x + threadIdx.x;
    if (i < n4x) { round4(x, g_xh, i); return; }
    i -= n4x;
    if (i < nW1) { round4(W1, g_w1h, i); return; }
    i -= nW1;
    if (i < nW2) { round4(W2, g_w2h, i); return; }
    i -= nW2;
    if (i < nW3) { round4(W3, g_w3h, i); return; }
}

// --------------------------------- GEMM ------------------------------------
// CTA tile 128x128, 256 threads, warp tile 32x64 (wm 0..3, wn 0..1).
// Stage = {A 16K | B 16K} = 32KB; 3 stages = 96KB -> 2 CTAs/SM.
// Fill addressing hoisted: per chunk each thread issues 8 cp.asyncs with
// precomputed swizzled smem offsets and global row offsets (+ c*128).

template<bool TANH, bool HALF_OUT>
__global__ void __launch_bounds__(256, 2)
gemm_mma(const __half* __restrict__ Ah, const __half* __restrict__ Bh,
         const float* __restrict__ bias,
         __half* __restrict__ Oh, float* __restrict__ Of,
         int M, int Nn, int K)
{
    extern __shared__ char smem[];
    constexpr int A_BYTES = 128 * 128;
    constexpr int STAGE   = 2 * A_BYTES;          // A + B
    constexpr int STAGES  = 3;

    const int tid = threadIdx.x;
    const int wid = tid >> 5;
    const int lid = tid & 31;
    const int wm  = wid & 3;
    const int wn  = wid >> 2;                     // 0..1
    const int sb  = wid & 3;                      // k-step stagger
    const int mBlock = blockIdx.y * 128;
    const int nBlock = blockIdx.x * 128;

    const uint32_t sbase = smem_u32(smem);

    // hoisted fill addressing (loop-invariant across chunks)
    uint32_t sOff[4], gOffA[4], gOffB[4];
    bool vA[4];
    #pragma unroll
    for (int i = 0; i < 4; i++) {
        int s = tid + i * 256;
        int row = s >> 3, byte = (s & 7) << 4;
        sOff[i] = SWZ((row << 7) + byte);
        int growA = mBlock + row;
        vA[i] = growA < M;
        gOffA[i] = (uint32_t)(vA[i] ? growA : 0) * (uint32_t)(K * 2) + byte;
        gOffB[i] = (uint32_t)(nBlock + row) * (uint32_t)(K * 2) + byte;
    }
    const char* A8 = (const char*)Ah;
    const char* B8 = (const char*)Bh;

    float acc[2][8][4];
    #pragma unroll
    for (int i = 0; i < 2; i++)
        #pragma unroll
        for (int j = 0; j < 8; j++)
            #pragma unroll
            for (int q = 0; q < 4; q++) acc[i][j][q] = 0.0f;

    const int NC = K >> 6;

    // prologue: chunks 0,1
    {
        #pragma unroll
        for (int i = 0; i < 4; i++)
            cp16z(sbase + sOff[i], A8 + gOffA[i], vA[i]);
        #pragma unroll
        for (int i = 0; i < 4; i++)
            cp16(sbase + A_BYTES + sOff[i], B8 + gOffB[i]);
        CP_COMMIT();
        if (1 < NC) {
            #pragma unroll
            for (int i = 0; i < 4; i++)
                cp16z(sbase + STAGE + sOff[i], A8 + gOffA[i] + 128, vA[i]);
            #pragma unroll
            for (int i = 0; i < 4; i++)
                cp16(sbase + STAGE + A_BYTES + sOff[i], B8 + gOffB[i] + 128);
        }
        CP_COMMIT();
    }

    const int aRow  = lid & 15;
    const int aByte = (lid >> 4) << 4;
    const int bRow  = (((lid >> 4) & 1) << 3) + (lid & 7);
    const int bByte = ((lid >> 3) & 1) << 4;

    const uint32_t aOffBase[2] = {
        (uint32_t)(((wm * 32 +  0 + aRow) << 7)),
        (uint32_t)(((wm * 32 + 16 + aRow) << 7)) };
    const uint32_t aSwz = ((aRow & 7) << 4);
    const uint32_t bOffBase[4] = {
        (uint32_t)(((wn * 64 +  0 + bRow) << 7)),
        (uint32_t)(((wn * 64 + 16 + bRow) << 7)),
        (uint32_t)(((wn * 64 + 32 + bRow) << 7)),
        (uint32_t)(((wn * 64 + 48 + bRow) << 7)) };
    const uint32_t bSwz = ((bRow & 7) << 4);

    for (int c = 0; c < NC; c++) {
        CP_WAIT(1);                    // chunk c resident
        __syncthreads();               // all warps done with stage (c-1)%3

        if (c + 2 < NC) {
            const uint32_t st   = sbase + ((c + 2) % STAGES) * STAGE;
            const uint32_t cOff = (uint32_t)(c + 2) << 7;
            #pragma unroll
            for (int i = 0; i < 4; i++)
                cp16z(st + sOff[i], A8 + gOffA[i] + cOff, vA[i]);
            #pragma unroll
            for (int i = 0; i < 4; i++)
                cp16(st + A_BYTES + sOff[i], B8 + gOffB[i] + cOff);
        }
        CP_COMMIT();

        const uint32_t stA = sbase + (c % STAGES) * STAGE;
        const uint32_t stB = stA + A_BYTES;

        #pragma unroll
        for (int ss = 0; ss < 4; ss++) {
            const int s = (ss + sb) & 3;
            uint32_t a[2][4], b[4][4];
            const uint32_t offA = (uint32_t)((32 * s + aByte)) ^ aSwz;
            const uint32_t offB = (uint32_t)((32 * s + bByte)) ^ bSwz;
            ldm_x4(a[0], stA + aOffBase[0] + offA);
            ldm_x4(a[1], stA + aOffBase[1] + offA);
            #pragma unroll
            for (int g = 0; g < 4; g++)
                ldm_x4(b[g], stB + bOffBase[g] + offB);

            #pragma unroll
            for (int mi = 0; mi < 2; mi++)
                #pragma unroll
                for (int ni = 0; ni < 8; ni++)
                    mma16816(acc[mi][ni], a[mi], b[ni >> 1][(ni & 1) * 2],
                             b[ni >> 1][(ni & 1) * 2 + 1]);
        }
    }

    // ------------------------------ epilogue --------------------------------
    const int lid4 = lid >> 2;
    const int lq   = (lid & 3) * 2;

    float bc[8][2];
    #pragma unroll
    for (int ni = 0; ni < 8; ni++) {
        float2 bv = *(const float2*)(bias + nBlock + wn * 64 + ni * 8 + lq);
        bc[ni][0] = bv.x; bc[ni][1] = bv.y;
    }

    #pragma unroll
    for (int mi = 0; mi < 2; mi++) {
        #pragma unroll
        for (int rr = 0; rr < 2; rr++) {
            const int row = mBlock + wm * 32 + mi * 16 + rr * 8 + lid4;
            if (row >= M) continue;
            #pragma unroll
            for (int ni = 0; ni < 8; ni++) {
                const int col = nBlock + wn * 64 + ni * 8 + lq;
                float v0 = acc[mi][ni][rr * 2 + 0] + bc[ni][0];
                float v1 = acc[mi][ni][rr * 2 + 1] + bc[ni][1];
                if (TANH) { v0 = fast_tanh(v0); v1 = fast_tanh(v1); }
                if (HALF_OUT) {
                    *(__half2*)(Oh + (size_t)row * Nn + col) =
                        __halves2half2(__float2half_rn(v0), __float2half_rn(v1));
                } else {
                    *(float2*)(Of + (size_t)row * Nn + col) = make_float2(v0, v1);
                }
            }
        }
    }
}

// ------------------------- CSR scatter-mean chain ---------------------------

__global__ void hist_kernel(const int* __restrict__ ei, int E)
{
    int e = blockIdx.x * blockDim.x + threadIdx.x;
    if (e < E) atomicAdd(&g_hist[ei[E + e]], 1);
}

__global__ void scan_local(int n)
{
    __shared__ int wsum[8];
    const int t = threadIdx.x, lane = t & 31, w = t >> 5;
    const int i = blockIdx.x * 256 + t;
    int v = (i < n) ? g_hist[i] : 0;
    int x = v;
    #pragma unroll
    for (int d = 1; d < 32; d <<= 1) {
        int y = __shfl_up_sync(0xFFFFFFFFu, x, d);
        if (lane >= d) x += y;
    }
    if (lane == 31) wsum[w] = x;
    __syncthreads();
    if (t == 0) {
        int run = 0;
        #pragma unroll
        for (int k = 0; k < 8; k++) { int tmp = wsum[k]; wsum[k] = run; run += tmp; }
        g_part[blockIdx.x] = run;
    }
    __syncthreads();
    if (i < n) g_off[i] = x - v + wsum[w];
}

__global__ void scan_top(int nb)
{
    __shared__ int s[512];
    const int t = threadIdx.x;
    s[t] = (t < nb) ? g_part[t] : 0;
    __syncthreads();
    #pragma unroll
    for (int d = 1; d < 512; d <<= 1) {
        int v = (t >= d) ? s[t - d] : 0;
        __syncthreads();
        s[t] += v;
        __syncthreads();
    }
    if (t < nb) g_part[t] = (t == 0) ? 0 : s[t - 1];
}

__global__ void scan_add(int n)
{
    int i = blockIdx.x * 256 + threadIdx.x;
    if (i < n) {
        int o = g_off[i] + g_part[blockIdx.x];
        g_off[i] = o;
        g_cur[i] = o;
    }
}

__global__ void reorder_kernel(const int* __restrict__ ei,
                               const float* __restrict__ alpha, int E)
{
    int e = blockIdx.x * blockDim.x + threadIdx.x;
    if (e >= E) return;
    float gate = 2.0f * fmaxf(alpha[e] - 0.5f, 0.0f);
    if (gate <= 0.0f) return;
    int dst = ei[E + e];
    int pos = atomicAdd(&g_cur[dst], 1);
    g_packed[pos] = make_uint2((unsigned)ei[e], __float_as_uint(gate));
}

// warp per dst: sum gated fp16 messages in fp32, divide by degree, write
__global__ void gather_kernel(const __half* __restrict__ hh,
                              float* __restrict__ out, int N)
{
    const int w    = (blockIdx.x * blockDim.x + threadIdx.x) >> 5;
    const int lane = threadIdx.x & 31;
    if (w >= N) return;
    const int start = g_off[w];
    const int end   = g_cur[w];
    const int deg   = g_hist[w];

    float4 acc = make_float4(0.f, 0.f, 0.f, 0.f);
    for (int i = start; i < end; i++) {
        uint2 p = g_packed[i];
        float g = __uint_as_float(p.y);
        uint2 hv = *(const uint2*)(hh + (size_t)p.x * 128 + lane * 4);
        float2 v01 = __half22float2(*(__half2*)&hv.x);
        float2 v23 = __half22float2(*(__half2*)&hv.y);
        acc.x += g * v01.x; acc.y += g * v01.y;
        acc.z += g * v23.x; acc.w += g * v23.y;
    }
    const float inv = 1.0f / fmaxf((float)deg, 1.0f);
    acc.x *= inv; acc.y *= inv; acc.z *= inv; acc.w *= inv;
    ((float4*)(out + (size_t)w * 128))[lane] = acc;
}

// --------------------------------- launch ----------------------------------

extern "C" void kernel_launch(void* const* d_in, const int* in_sizes, int n_in,
                              void* d_out, int out_size)
{
    const float* x     = (const float*)d_in[0];
    const float* alpha = (const float*)d_in[1];
    const int*   ei    = (const int*)  d_in[2];
    const float* W1 = (const float*)d_in[4];
    const float* b1 = (const float*)d_in[5];
    const float* W2 = (const float*)d_in[6];
    const float* b2 = (const float*)d_in[7];
    const float* W3 = (const float*)d_in[8];
    const float* b3 = (const float*)d_in[9];
    float* out = (float*)d_out;

    const int N = in_sizes[0] / 256;
    const int E = in_sizes[1];

    __half *xh, *h1h, *h2h, *hh, *w1h, *w2h, *w3h;
    int *hist;
    cudaGetSymbolAddress((void**)&xh,   g_xh);
    cudaGetSymbolAddress((void**)&h1h,  g_h1h);
    cudaGetSymbolAddress((void**)&h2h,  g_h2h);
    cudaGetSymbolAddress((void**)&hh,   g_hh);
    cudaGetSymbolAddress((void**)&w1h,  g_w1h);
    cudaGetSymbolAddress((void**)&w2h,  g_w2h);
    cudaGetSymbolAddress((void**)&w3h,  g_w3h);
    cudaGetSymbolAddress((void**)&hist, g_hist);

    const int SMEM_G = 3 * 2 * 16384;     // 98304 bytes; 2 CTAs/SM
    cudaFuncSetAttribute(gemm_mma<true,  true>,
                         cudaFuncAttributeMaxDynamicSharedMemorySize, SMEM_G);
    cudaFuncSetAttribute(gemm_mma<false, true>,
                         cudaFuncAttributeMaxDynamicSharedMemorySize, SMEM_G);

    cudaMemsetAsync(hist, 0, (size_t)N * sizeof(int));

    const int mt = (N + 127) / 128;
    const int nb = (N + 255) / 256;
    const int n4x = (N * 256) / 4;
    const int splitTot = n4x + 512 * 256 / 4 + 256 * 512 / 4 + 128 * 256 / 4;

    // kernel #1
    split_all<<<(splitTot + 255) / 256, 256>>>(x, W1, W2, W3, n4x);
    // kernel #2
    gemm_mma<true,  true><<<dim3(4, mt), 256, SMEM_G>>>(
        xh, w1h, b1, h1h, nullptr, N, 512, 256);
    // kernel #3
    hist_kernel<<<(E + 255) / 256, 256>>>(ei, E);
    // kernel #4  <-- ncu capture slot: gemm2
    gemm_mma<true,  true><<<dim3(2, mt), 256, SMEM_G>>>(
        h1h, w2h, b2, h2h, nullptr, N, 256, 512);
    // kernel #5
    scan_local<<<nb, 256>>>(N);
    // kernel #6
    scan_top<<<1, 512>>>(nb);
    // kernel #7
    scan_add<<<nb, 256>>>(N);
    // kernel #8
    reorder_kernel<<<(E + 255) / 256, 256>>>(ei, alpha, E);
    // kernel #9
    gemm_mma<false, true><<<dim3(1, mt), 256, SMEM_G>>>(
        h2h, w3h, b3, hh, nullptr, N, 128, 256);
    // kernel #10
    gather_kernel<<<(N * 32 + 255) / 256, 256>>>(hh, out, N);
}

// round 13
// speedup vs baseline: 5.5336x; 1.0301x over previous
#include <cuda_runtime.h>
#include <cuda_fp16.h>
#include <math.h>
#include <stdint.h>

// ---------------------------------------------------------------------------
// FilterGNN round 13: R12 GEMMs (hoisted fill addressing) + stream fork/join:
// the CSR scatter-prep chain (hist/scan/reorder) runs on a side stream
// concurrently with split+GEMM1..3; gather joins both.
// Host launch order: split#1 hist#2 scanL#3 GEMM1#4(capture) scanT#5 scanA#6
//                    GEMM2#7 reorder#8 GEMM3#9 gather#10
// ---------------------------------------------------------------------------

#define MAXN 100000
#define MAXE 640000

__device__ __align__(16) __half g_xh [MAXN * 256];
__device__ __align__(16) __half g_h1h[MAXN * 512];
__device__ __align__(16) __half g_h2h[MAXN * 256];
__device__ __align__(16) __half g_hh [MAXN * 128];
__device__ __align__(16) __half g_w1h[512 * 256];
__device__ __align__(16) __half g_w2h[256 * 512];
__device__ __align__(16) __half g_w3h[128 * 256];

__device__ int   g_hist[MAXN];
__device__ int   g_off [MAXN];
__device__ int   g_cur [MAXN];
__device__ int   g_part[512];
__device__ uint2 g_packed[MAXE];

// ------------------------------- helpers -----------------------------------

__device__ __forceinline__ uint32_t smem_u32(const void* p) {
    uint32_t a;
    asm("{ .reg .u64 t; cvta.to.shared.u64 t, %1; cvt.u32.u64 %0, t; }"
        : "=r"(a) : "l"(p));
    return a;
}

#define SWZ(off) ((off) ^ (((off) >> 3) & 0x70))

__device__ __forceinline__ void cp16(uint32_t dst, const void* src) {
    asm volatile("cp.async.cg.shared.global [%0], [%1], 16;\n"
                 :: "r"(dst), "l"(src));
}
__device__ __forceinline__ void cp16z(uint32_t dst, const void* src, bool valid) {
    asm volatile("cp.async.cg.shared.global [%0], [%1], 16, %2;\n"
                 :: "r"(dst), "l"(src), "r"(valid ? 16u : 0u));
}
#define CP_COMMIT()  asm volatile("cp.async.commit_group;\n" ::: "memory")
#define CP_WAIT(n)   asm volatile("cp.async.wait_group %0;\n" :: "n"(n) : "memory")

__device__ __forceinline__ void ldm_x4(uint32_t r[4], uint32_t addr) {
    asm volatile("ldmatrix.sync.aligned.m8n8.x4.shared.b16 {%0,%1,%2,%3}, [%4];"
                 : "=r"(r[0]), "=r"(r[1]), "=r"(r[2]), "=r"(r[3]) : "r"(addr));
}

__device__ __forceinline__ void mma16816(float c[4], const uint32_t a[4],
                                         uint32_t b0, uint32_t b1) {
    asm volatile(
        "mma.sync.aligned.m16n8k16.row.col.f32.f16.f16.f32 "
        "{%0,%1,%2,%3}, {%4,%5,%6,%7}, {%8,%9}, {%0,%1,%2,%3};"
        : "+f"(c[0]), "+f"(c[1]), "+f"(c[2]), "+f"(c[3])
        : "r"(a[0]), "r"(a[1]), "r"(a[2]), "r"(a[3]), "r"(b0), "r"(b1));
}

// tanh(x) = 1 - 2 / (exp2(x * 2/ln2) + 1); MUFU ex2/rcp are ~2^-22 accurate.
__device__ __forceinline__ float fast_tanh(float x) {
    float e, r;
    asm("ex2.approx.f32 %0, %1;" : "=f"(e) : "f"(x * 2.885390081777927f));
    asm("rcp.approx.f32 %0, %1;" : "=f"(r) : "f"(e + 1.0f));
    return fmaf(-2.0f, r, 1.0f);
}

// ------------------------------ fused round --------------------------------

__device__ __forceinline__ void round4(const float* __restrict__ a,
                                       __half* __restrict__ hi, int i)
{
    float4 v = ((const float4*)a)[i];
    __half h[4] = { __float2half_rn(v.x), __float2half_rn(v.y),
                    __float2half_rn(v.z), __float2half_rn(v.w) };
    ((uint2*)hi)[i] = *(uint2*)h;
}

__global__ void split_all(const float* __restrict__ x,
                          const float* __restrict__ W1,
                          const float* __restrict__ W2,
                          const float* __restrict__ W3, int n4x)
{
    const int nW1 = 512 * 256 / 4, nW2 = 256 * 512 / 4, nW3 = 128 * 256 / 4;
    int i = blockIdx.x * blockDim.x + threadIdx.x;
    if (i < n4x) { round4(x, g_xh, i); return; }
    i -= n4x;
    if (i < nW1) { round4(W1, g_w1h, i); return; }
    i -= nW1;
    if (i < nW2) { round4(W2, g_w2h, i); return; }
    i -= nW2;
    if (i < nW3) { round4(W3, g_w3h, i); return; }
}

// --------------------------------- GEMM ------------------------------------
// CTA tile 128x128, 256 threads, warp tile 32x64 (wm 0..3, wn 0..1).
// Stage = {A 16K | B 16K} = 32KB; 3 stages = 96KB -> 2 CTAs/SM.

template<bool TANH, bool HALF_OUT>
__global__ void __launch_bounds__(256, 2)
gemm_mma(const __half* __restrict__ Ah, const __half* __restrict__ Bh,
         const float* __restrict__ bias,
         __half* __restrict__ Oh, float* __restrict__ Of,
         int M, int Nn, int K)
{
    extern __shared__ char smem[];
    constexpr int A_BYTES = 128 * 128;
    constexpr int STAGE   = 2 * A_BYTES;          // A + B
    constexpr int STAGES  = 3;

    const int tid = threadIdx.x;
    const int wid = tid >> 5;
    const int lid = tid & 31;
    const int wm  = wid & 3;
    const int wn  = wid >> 2;                     // 0..1
    const int sb  = wid & 3;                      // k-step stagger
    const int mBlock = blockIdx.y * 128;
    const int nBlock = blockIdx.x * 128;

    const uint32_t sbase = smem_u32(smem);

    // hoisted fill addressing (loop-invariant across chunks)
    uint32_t sOff[4], gOffA[4], gOffB[4];
    bool vA[4];
    #pragma unroll
    for (int i = 0; i < 4; i++) {
        int s = tid + i * 256;
        int row = s >> 3, byte = (s & 7) << 4;
        sOff[i] = SWZ((row << 7) + byte);
        int growA = mBlock + row;
        vA[i] = growA < M;
        gOffA[i] = (uint32_t)(vA[i] ? growA : 0) * (uint32_t)(K * 2) + byte;
        gOffB[i] = (uint32_t)(nBlock + row) * (uint32_t)(K * 2) + byte;
    }
    const char* A8 = (const char*)Ah;
    const char* B8 = (const char*)Bh;

    float acc[2][8][4];
    #pragma unroll
    for (int i = 0; i < 2; i++)
        #pragma unroll
        for (int j = 0; j < 8; j++)
            #pragma unroll
            for (int q = 0; q < 4; q++) acc[i][j][q] = 0.0f;

    const int NC = K >> 6;

    // prologue: chunks 0,1
    {
        #pragma unroll
        for (int i = 0; i < 4; i++)
            cp16z(sbase + sOff[i], A8 + gOffA[i], vA[i]);
        #pragma unroll
        for (int i = 0; i < 4; i++)
            cp16(sbase + A_BYTES + sOff[i], B8 + gOffB[i]);
        CP_COMMIT();
        if (1 < NC) {
            #pragma unroll
            for (int i = 0; i < 4; i++)
                cp16z(sbase + STAGE + sOff[i], A8 + gOffA[i] + 128, vA[i]);
            #pragma unroll
            for (int i = 0; i < 4; i++)
                cp16(sbase + STAGE + A_BYTES + sOff[i], B8 + gOffB[i] + 128);
        }
        CP_COMMIT();
    }

    const int aRow  = lid & 15;
    const int aByte = (lid >> 4) << 4;
    const int bRow  = (((lid >> 4) & 1) << 3) + (lid & 7);
    const int bByte = ((lid >> 3) & 1) << 4;

    const uint32_t aOffBase[2] = {
        (uint32_t)(((wm * 32 +  0 + aRow) << 7)),
        (uint32_t)(((wm * 32 + 16 + aRow) << 7)) };
    const uint32_t aSwz = ((aRow & 7) << 4);
    const uint32_t bOffBase[4] = {
        (uint32_t)(((wn * 64 +  0 + bRow) << 7)),
        (uint32_t)(((wn * 64 + 16 + bRow) << 7)),
        (uint32_t)(((wn * 64 + 32 + bRow) << 7)),
        (uint32_t)(((wn * 64 + 48 + bRow) << 7)) };
    const uint32_t bSwz = ((bRow & 7) << 4);

    for (int c = 0; c < NC; c++) {
        CP_WAIT(1);                    // chunk c resident
        __syncthreads();               // all warps done with stage (c-1)%3

        if (c + 2 < NC) {
            const uint32_t st   = sbase + ((c + 2) % STAGES) * STAGE;
            const uint32_t cOff = (uint32_t)(c + 2) << 7;
            #pragma unroll
            for (int i = 0; i < 4; i++)
                cp16z(st + sOff[i], A8 + gOffA[i] + cOff, vA[i]);
            #pragma unroll
            for (int i = 0; i < 4; i++)
                cp16(st + A_BYTES + sOff[i], B8 + gOffB[i] + cOff);
        }
        CP_COMMIT();

        const uint32_t stA = sbase + (c % STAGES) * STAGE;
        const uint32_t stB = stA + A_BYTES;

        #pragma unroll
        for (int ss = 0; ss < 4; ss++) {
            const int s = (ss + sb) & 3;
            uint32_t a[2][4], b[4][4];
            const uint32_t offA = (uint32_t)((32 * s + aByte)) ^ aSwz;
            const uint32_t offB = (uint32_t)((32 * s + bByte)) ^ bSwz;
            ldm_x4(a[0], stA + aOffBase[0] + offA);
            ldm_x4(a[1], stA + aOffBase[1] + offA);
            #pragma unroll
            for (int g = 0; g < 4; g++)
                ldm_x4(b[g], stB + bOffBase[g] + offB);

            #pragma unroll
            for (int mi = 0; mi < 2; mi++)
                #pragma unroll
                for (int ni = 0; ni < 8; ni++)
                    mma16816(acc[mi][ni], a[mi], b[ni >> 1][(ni & 1) * 2],
                             b[ni >> 1][(ni & 1) * 2 + 1]);
        }
    }

    // ------------------------------ epilogue --------------------------------
    const int lid4 = lid >> 2;
    const int lq   = (lid & 3) * 2;

    float bc[8][2];
    #pragma unroll
    for (int ni = 0; ni < 8; ni++) {
        float2 bv = *(const float2*)(bias + nBlock + wn * 64 + ni * 8 + lq);
        bc[ni][0] = bv.x; bc[ni][1] = bv.y;
    }

    #pragma unroll
    for (int mi = 0; mi < 2; mi++) {
        #pragma unroll
        for (int rr = 0; rr < 2; rr++) {
            const int row = mBlock + wm * 32 + mi * 16 + rr * 8 + lid4;
            if (row >= M) continue;
            #pragma unroll
            for (int ni = 0; ni < 8; ni++) {
                const int col = nBlock + wn * 64 + ni * 8 + lq;
                float v0 = acc[mi][ni][rr * 2 + 0] + bc[ni][0];
                float v1 = acc[mi][ni][rr * 2 + 1] + bc[ni][1];
                if (TANH) { v0 = fast_tanh(v0); v1 = fast_tanh(v1); }
                if (HALF_OUT) {
                    *(__half2*)(Oh + (size_t)row * Nn + col) =
                        __halves2half2(__float2half_rn(v0), __float2half_rn(v1));
                } else {
                    *(float2*)(Of + (size_t)row * Nn + col) = make_float2(v0, v1);
                }
            }
        }
    }
}

// ------------------------- CSR scatter-mean chain ---------------------------

__global__ void hist_kernel(const int* __restrict__ ei, int E)
{
    int e = blockIdx.x * blockDim.x + threadIdx.x;
    if (e < E) atomicAdd(&g_hist[ei[E + e]], 1);
}

__global__ void scan_local(int n)
{
    __shared__ int wsum[8];
    const int t = threadIdx.x, lane = t & 31, w = t >> 5;
    const int i = blockIdx.x * 256 + t;
    int v = (i < n) ? g_hist[i] : 0;
    int x = v;
    #pragma unroll
    for (int d = 1; d < 32; d <<= 1) {
        int y = __shfl_up_sync(0xFFFFFFFFu, x, d);
        if (lane >= d) x += y;
    }
    if (lane == 31) wsum[w] = x;
    __syncthreads();
    if (t == 0) {
        int run = 0;
        #pragma unroll
        for (int k = 0; k < 8; k++) { int tmp = wsum[k]; wsum[k] = run; run += tmp; }
        g_part[blockIdx.x] = run;
    }
    __syncthreads();
    if (i < n) g_off[i] = x - v + wsum[w];
}

__global__ void scan_top(int nb)
{
    __shared__ int s[512];
    const int t = threadIdx.x;
    s[t] = (t < nb) ? g_part[t] : 0;
    __syncthreads();
    #pragma unroll
    for (int d = 1; d < 512; d <<= 1) {
        int v = (t >= d) ? s[t - d] : 0;
        __syncthreads();
        s[t] += v;
        __syncthreads();
    }
    if (t < nb) g_part[t] = (t == 0) ? 0 : s[t - 1];
}

__global__ void scan_add(int n)
{
    int i = blockIdx.x * 256 + threadIdx.x;
    if (i < n) {
        int o = g_off[i] + g_part[blockIdx.x];
        g_off[i] = o;
        g_cur[i] = o;
    }
}

__global__ void reorder_kernel(const int* __restrict__ ei,
                               const float* __restrict__ alpha, int E)
{
    int e = blockIdx.x * blockDim.x + threadIdx.x;
    if (e >= E) return;
    float gate = 2.0f * fmaxf(alpha[e] - 0.5f, 0.0f);
    if (gate <= 0.0f) return;
    int dst = ei[E + e];
    int pos = atomicAdd(&g_cur[dst], 1);
    g_packed[pos] = make_uint2((unsigned)ei[e], __float_as_uint(gate));
}

// warp per dst: sum gated fp16 messages in fp32, divide by degree, write
__global__ void gather_kernel(const __half* __restrict__ hh,
                              float* __restrict__ out, int N)
{
    const int w    = (blockIdx.x * blockDim.x + threadIdx.x) >> 5;
    const int lane = threadIdx.x & 31;
    if (w >= N) return;
    const int start = g_off[w];
    const int end   = g_cur[w];
    const int deg   = g_hist[w];

    float4 acc = make_float4(0.f, 0.f, 0.f, 0.f);
    for (int i = start; i < end; i++) {
        uint2 p = g_packed[i];
        float g = __uint_as_float(p.y);
        uint2 hv = *(const uint2*)(hh + (size_t)p.x * 128 + lane * 4);
        float2 v01 = __half22float2(*(__half2*)&hv.x);
        float2 v23 = __half22float2(*(__half2*)&hv.y);
        acc.x += g * v01.x; acc.y += g * v01.y;
        acc.z += g * v23.x; acc.w += g * v23.y;
    }
    const float inv = 1.0f / fmaxf((float)deg, 1.0f);
    acc.x *= inv; acc.y *= inv; acc.z *= inv; acc.w *= inv;
    ((float4*)(out + (size_t)w * 128))[lane] = acc;
}

// --------------------------------- launch ----------------------------------

extern "C" void kernel_launch(void* const* d_in, const int* in_sizes, int n_in,
                              void* d_out, int out_size)
{
    const float* x     = (const float*)d_in[0];
    const float* alpha = (const float*)d_in[1];
    const int*   ei    = (const int*)  d_in[2];
    const float* W1 = (const float*)d_in[4];
    const float* b1 = (const float*)d_in[5];
    const float* W2 = (const float*)d_in[6];
    const float* b2 = (const float*)d_in[7];
    const float* W3 = (const float*)d_in[8];
    const float* b3 = (const float*)d_in[9];
    float* out = (float*)d_out;

    const int N = in_sizes[0] / 256;
    const int E = in_sizes[1];

    __half *xh, *h1h, *h2h, *hh, *w1h, *w2h, *w3h;
    int *hist;
    cudaGetSymbolAddress((void**)&xh,   g_xh);
    cudaGetSymbolAddress((void**)&h1h,  g_h1h);
    cudaGetSymbolAddress((void**)&h2h,  g_h2h);
    cudaGetSymbolAddress((void**)&hh,   g_hh);
    cudaGetSymbolAddress((void**)&w1h,  g_w1h);
    cudaGetSymbolAddress((void**)&w2h,  g_w2h);
    cudaGetSymbolAddress((void**)&w3h,  g_w3h);
    cudaGetSymbolAddress((void**)&hist, g_hist);

    const int SMEM_G = 3 * 2 * 16384;     // 98304 bytes; 2 CTAs/SM
    cudaFuncSetAttribute(gemm_mma<true,  true>,
                         cudaFuncAttributeMaxDynamicSharedMemorySize, SMEM_G);
    cudaFuncSetAttribute(gemm_mma<false, true>,
                         cudaFuncAttributeMaxDynamicSharedMemorySize, SMEM_G);

    const int mt = (N + 127) / 128;
    const int nb = (N + 255) / 256;
    const int n4x = (N * 256) / 4;
    const int splitTot = n4x + 512 * 256 / 4 + 256 * 512 / 4 + 128 * 256 / 4;

    // fork a side stream into the capture for the CSR prep chain
    cudaStream_t s1;
    cudaStreamCreateWithFlags(&s1, cudaStreamNonBlocking);
    cudaEvent_t evFork, evJoin;
    cudaEventCreateWithFlags(&evFork, cudaEventDisableTiming);
    cudaEventCreateWithFlags(&evJoin, cudaEventDisableTiming);

    cudaEventRecord(evFork, 0);
    cudaStreamWaitEvent(s1, evFork, 0);

    cudaMemsetAsync(hist, 0, (size_t)N * sizeof(int), s1);

    // main #1
    split_all<<<(splitTot + 255) / 256, 256>>>(x, W1, W2, W3, n4x);
    // side #2
    hist_kernel<<<(E + 255) / 256, 256, 0, s1>>>(ei, E);
    // side #3
    scan_local<<<nb, 256, 0, s1>>>(N);
    // main #4  <-- ncu capture slot: gemm1
    gemm_mma<true,  true><<<dim3(4, mt), 256, SMEM_G>>>(
        xh, w1h, b1, h1h, nullptr, N, 512, 256);
    // side #5
    scan_top<<<1, 512, 0, s1>>>(nb);
    // side #6
    scan_add<<<nb, 256, 0, s1>>>(N);
    // main #7
    gemm_mma<true,  true><<<dim3(2, mt), 256, SMEM_G>>>(
        h1h, w2h, b2, h2h, nullptr, N, 256, 512);
    // side #8
    reorder_kernel<<<(E + 255) / 256, 256, 0, s1>>>(ei, alpha, E);
    cudaEventRecord(evJoin, s1);
    // main #9
    gemm_mma<false, true><<<dim3(1, mt), 256, SMEM_G>>>(
        h2h, w3h, b3, hh, nullptr, N, 128, 256);
    // join: gather needs reorder (side) + gemm3 (main)
    cudaStreamWaitEvent(0, evJoin, 0);
    // main #10
    gather_kernel<<<(N * 32 + 255) / 256, 256>>>(hh, out, N);
}